// round 10
// baseline (speedup 1.0000x reference)
#include <cuda_runtime.h>
#include <cstdint>

// Problem constants
#define BB   2
#define LL   2048
#define HH   1024
#define NHH  4
#define KD   512
#define VD   1024
#define DKK  128
#define DVV  256
#define PRR  32
#define GRR  64
#define MT   4096   // total tokens B*L

// ---------------- scratch (static __device__, no allocation) ----------------
__device__ float g_ax[MT * HH];          // lerped x with mu_x
__device__ float g_xp[MT * 160];         // tanh proj, 5*PR
__device__ float g_amix[5][MT * HH];     // lerped inputs for r,w,k,v,g
__device__ float g_r [MT * KD];
__device__ float g_k [MT * KD];
__device__ float g_v [MT * VD];
__device__ float g_g [MT * VD];
__device__ float g_wd[MT * GRR];
__device__ float g_ew[MT * KD];          // exp(-exp(w_raw))
__device__ float g_c [MT * NHH];         // bonus scalar per (token, head)
__device__ float g_o [MT * VD];          // recurrence output
__device__ float g_og[MT * VD];          // after LN + gate

// ---------------- elementwise: ax = x + (xprev - x)*mu_x ----------------
__global__ void ax_kernel(const float* __restrict__ x,
                          const float* __restrict__ mu_x,
                          float* __restrict__ ax) {
    size_t i = (size_t)blockIdx.x * blockDim.x + threadIdx.x;
    if (i >= (size_t)MT * HH) return;
    int n = (int)(i & (HH - 1));
    size_t m = i >> 10;
    float mu = mu_x[n];
    float xv = x[i];
    float xp = ((m & (LL - 1)) == 0) ? 0.f : x[i - HH];
    ax[i] = xv + (xp - xv) * mu;
}

// ---------------- tf32 tensor-core GEMM ------------------------------------
// C = epi(act(A @ W^T + bias)).  A:[M,K] K-contig, W:[N,K] K-contig.
// CTA: 128 threads = 4 warps (2x2), warp tile 64x64, CTA tile 128x128, BK=16.
// Fragment-major smem: A fragment = one LDS.128; B pair-fragment = one LDS.128.
// XOR lane swizzle + parity slot swizzle make producer STS and consumer LDS
// both 32-bank conflict-free (bank bits are a bijection of thread bits).
struct GemmZ  { const float* A; const float* W; float* C; const float* bias; };
struct GemmZ5 { GemmZ z[5]; };

__device__ __forceinline__ uint32_t f2tf32(float v) {
    uint32_t t;
    asm("cvt.rna.tf32.f32 %0, %1;" : "=r"(t) : "f"(v));
    return t;
}

__global__ __launch_bounds__(128, 2)
void tgemm_kernel(GemmZ5 dz, int lda, int ldw, int ldc,
                  int M, int N, int Kdim,
                  int act, int epi,
                  const float* __restrict__ xsrc) {
    const GemmZ gd = dz.z[blockIdx.z];
    const float* A = gd.A;
    const float* W = gd.W;
    float* C = gd.C;
    const float* bias = gd.bias;

    // layout: block (h,mb): base (h*8+mb)*128 words; word = phys_lane*4 + slot
    __shared__ __align__(16) float As[2][2048];
    __shared__ __align__(16) float Bs[2][2048];

    int tid = threadIdx.x;            // 0..127
    int mBase = blockIdx.y * 128;
    int nBase = blockIdx.x * 128;
    int w = tid >> 5, lane = tid & 31;
    int wm = (w >> 1) * 64;           // warp m-offset (0/64)
    int wn = (w & 1) * 64;            // warp n-offset (0/64)
    int grp = lane >> 2, tig = lane & 3;
    int plane = lane ^ (lane >> 3);   // consumer physical lane

    float acc[4][8][4];
#pragma unroll
    for (int mi = 0; mi < 4; mi++)
#pragma unroll
        for (int ni = 0; ni < 8; ni++)
#pragma unroll
            for (int q = 0; q < 4; q++) acc[mi][ni][q] = 0.f;

    // producer constants (thread = one A row, one B row)
    int rA = tid & 15, mbA = tid >> 4;            // A: row rA within block mbA
    int rl7A = 4 * (rA & 7);
    int sA0 = (rA >> 3) ^ ((mbA & 1) << 1);       // slot for kk2=0
    int sA1 = ((rA >> 3) + 2) ^ ((mbA & 1) << 1); // slot for kk2=1
    int rB = tid & 7;                             // B: col tid -> 8x8 block
    int nbl = tid >> 3;                           // local n-block 0..15
    int nbpB = nbl >> 1, nboB = nbl & 1;
    int rl7B = 4 * rB;
    int sB0 = (2 * nboB) ^ (nbpB & 1);            // slot for kk2=0
    int sB1 = (2 * nboB + 1) ^ (nbpB & 1);        // slot for kk2=1

    int nt = Kdim >> 4;
    bool bok = (nBase + tid) < N;
    const float* apBase = A + (size_t)(mBase + tid) * lda;
    const float* wpBase = W + (size_t)(nBase + tid) * ldw;

    float av[16], bv[16];
    // prologue: load + stage tile 0
    {
        *(float4*)(av)      = *(const float4*)(apBase);
        *(float4*)(av + 4)  = *(const float4*)(apBase + 4);
        *(float4*)(av + 8)  = *(const float4*)(apBase + 8);
        *(float4*)(av + 12) = *(const float4*)(apBase + 12);
        if (bok) {
            *(float4*)(bv)      = *(const float4*)(wpBase);
            *(float4*)(bv + 4)  = *(const float4*)(wpBase + 4);
            *(float4*)(bv + 8)  = *(const float4*)(wpBase + 8);
            *(float4*)(bv + 12) = *(const float4*)(wpBase + 12);
        } else {
#pragma unroll
            for (int j = 0; j < 16; j++) bv[j] = 0.f;
        }
#pragma unroll
        for (int j = 0; j < 16; j++) {
            int h = j >> 3, kk3 = j & 3, kk2 = (j >> 2) & 1;
            int llA = rl7A + kk3;
            int llB = rl7B + kk3;
            As[0][(h * 8 + mbA) * 128 + (llA ^ (llA >> 3)) * 4 + (kk2 ? sA1 : sA0)]
                = __uint_as_float(f2tf32(av[j]));
            Bs[0][(h * 8 + nbpB) * 128 + (llB ^ (llB >> 3)) * 4 + (kk2 ? sB1 : sB0)]
                = __uint_as_float(f2tf32(bv[j]));
        }
    }
    __syncthreads();

    int mbBase = (w >> 1) * 4;   // even
    int npBase = (w & 1) * 4;    // even

    for (int kt = 0; kt < nt; kt++) {
        int cur = kt & 1;
        bool more = (kt + 1 < nt);
        if (more) {
            const float* ap = apBase + (kt + 1) * 16;
            *(float4*)(av)      = *(const float4*)(ap);
            *(float4*)(av + 4)  = *(const float4*)(ap + 4);
            *(float4*)(av + 8)  = *(const float4*)(ap + 8);
            *(float4*)(av + 12) = *(const float4*)(ap + 12);
            if (bok) {
                const float* wp = wpBase + (kt + 1) * 16;
                *(float4*)(bv)      = *(const float4*)(wp);
                *(float4*)(bv + 4)  = *(const float4*)(wp + 4);
                *(float4*)(bv + 8)  = *(const float4*)(wp + 8);
                *(float4*)(bv + 12) = *(const float4*)(wp + 12);
            }
        }
#pragma unroll
        for (int hh = 0; hh < 2; hh++) {
            float4 aq[4], bq[4];
#pragma unroll
            for (int mi = 0; mi < 4; mi++)
                aq[mi] = *(const float4*)&As[cur][(hh * 8 + mbBase + mi) * 128 + plane * 4];
#pragma unroll
            for (int p = 0; p < 4; p++)
                bq[p] = *(const float4*)&Bs[cur][(hh * 8 + npBase + p) * 128 + plane * 4];

            uint32_t af[4][4], bf[8][2];
#pragma unroll
            for (int mi = 0; mi < 4; mi++) {
                if (mi & 1) {   // mb odd: slots stored XOR 2 -> swap halves
                    af[mi][0] = __float_as_uint(aq[mi].z);
                    af[mi][1] = __float_as_uint(aq[mi].w);
                    af[mi][2] = __float_as_uint(aq[mi].x);
                    af[mi][3] = __float_as_uint(aq[mi].y);
                } else {
                    af[mi][0] = __float_as_uint(aq[mi].x);
                    af[mi][1] = __float_as_uint(aq[mi].y);
                    af[mi][2] = __float_as_uint(aq[mi].z);
                    af[mi][3] = __float_as_uint(aq[mi].w);
                }
            }
#pragma unroll
            for (int p = 0; p < 4; p++) {
                if (p & 1) {    // nbp odd: slots stored XOR 1 -> swap within pairs
                    bf[2 * p][0]     = __float_as_uint(bq[p].y);
                    bf[2 * p][1]     = __float_as_uint(bq[p].x);
                    bf[2 * p + 1][0] = __float_as_uint(bq[p].w);
                    bf[2 * p + 1][1] = __float_as_uint(bq[p].z);
                } else {
                    bf[2 * p][0]     = __float_as_uint(bq[p].x);
                    bf[2 * p][1]     = __float_as_uint(bq[p].y);
                    bf[2 * p + 1][0] = __float_as_uint(bq[p].z);
                    bf[2 * p + 1][1] = __float_as_uint(bq[p].w);
                }
            }
#pragma unroll
            for (int mi = 0; mi < 4; mi++)
#pragma unroll
                for (int ni = 0; ni < 8; ni++) {
                    asm volatile(
                        "mma.sync.aligned.m16n8k8.row.col.f32.tf32.tf32.f32 "
                        "{%0,%1,%2,%3}, {%4,%5,%6,%7}, {%8,%9}, {%0,%1,%2,%3};"
                        : "+f"(acc[mi][ni][0]), "+f"(acc[mi][ni][1]),
                          "+f"(acc[mi][ni][2]), "+f"(acc[mi][ni][3])
                        : "r"(af[mi][0]), "r"(af[mi][1]),
                          "r"(af[mi][2]), "r"(af[mi][3]),
                          "r"(bf[ni][0]), "r"(bf[ni][1]));
                }
        }
        if (more) {
            int nxt = cur ^ 1;
#pragma unroll
            for (int j = 0; j < 16; j++) {
                int h = j >> 3, kk3 = j & 3, kk2 = (j >> 2) & 1;
                int llA = rl7A + kk3;
                int llB = rl7B + kk3;
                As[nxt][(h * 8 + mbA) * 128 + (llA ^ (llA >> 3)) * 4 + (kk2 ? sA1 : sA0)]
                    = __uint_as_float(f2tf32(av[j]));
                Bs[nxt][(h * 8 + nbpB) * 128 + (llB ^ (llB >> 3)) * 4 + (kk2 ? sB1 : sB0)]
                    = __uint_as_float(f2tf32(bv[j]));
            }
        }
        __syncthreads();
    }

    // epilogue: float2-vectorized (paired accumulator cols are adjacent n)
#pragma unroll
    for (int mi = 0; mi < 4; mi++) {
#pragma unroll
        for (int ni = 0; ni < 8; ni++) {
            int m0 = mBase + wm + mi * 16 + grp;
            int n0 = nBase + wn + ni * 8 + tig * 2;
            if (n0 >= N) continue;
#pragma unroll
            for (int hr = 0; hr < 2; hr++) {
                int m = m0 + hr * 8;
                float vx = acc[mi][ni][hr * 2 + 0];
                float vy = acc[mi][ni][hr * 2 + 1];
                if (bias) { vx += bias[n0]; vy += bias[n0 + 1]; }
                if (act)  { vx = tanhf(vx); vy = tanhf(vy); }
                if (epi == 1) {
                    float2 xv = *(const float2*)&xsrc[(size_t)m * HH + n0];
                    float2 xp = ((m & (LL - 1)) == 0) ? make_float2(0.f, 0.f)
                              : *(const float2*)&xsrc[(size_t)(m - 1) * HH + n0];
                    vx = xv.x + (xp.x - xv.x) * vx;
                    vy = xv.y + (xp.y - xv.y) * vy;
                } else if (epi == 2) {
                    vx = expf(-expf(vx));
                    vy = expf(-expf(vy));
                }
                *(float2*)&C[(size_t)m * ldc + n0] = make_float2(vx, vy);
            }
        }
    }
}

// ---------------- per-(token,head) bonus scalar c = sum r*bonus*k ----------
__global__ void c_kernel(const float* __restrict__ r,
                         const float* __restrict__ kk,
                         const float* __restrict__ bonus,
                         float* __restrict__ c) {
    int t = blockIdx.x;
    int h = threadIdx.x >> 5, lane = threadIdx.x & 31;
    const float* rp = r  + (size_t)t * KD + h * DKK;
    const float* kp = kk + (size_t)t * KD + h * DKK;
    const float* bp = bonus + h * DKK;
    float s = 0.f;
#pragma unroll
    for (int j = lane; j < DKK; j += 32) s += rp[j] * bp[j] * kp[j];
#pragma unroll
    for (int o = 16; o; o >>= 1) s += __shfl_xor_sync(0xffffffffu, s, o);
    if (!lane) c[(size_t)t * NHH + h] = s;
}

// ---------------- sequential recurrence (128 CTAs, software-pipelined) ----
#define OFF_R 0
#define OFF_K 128
#define OFF_W 256
#define OFF_V 384
#define OFF_C 400
__global__ __launch_bounds__(256)
void recur_kernel(const float* __restrict__ r,
                  const float* __restrict__ kk,
                  const float* __restrict__ ew,
                  const float* __restrict__ v,
                  const float* __restrict__ c,
                  float* __restrict__ o) {
    int blk = blockIdx.x;
    int chain = blk >> 4;       // 0..7
    int vb = blk & 15;          // 16-col block
    int b = chain >> 2, h = chain & 3;
    int tid = threadIdx.x;
    int kg = tid >> 4;          // 0..15, owns k-range kg*8..kg*8+7
    int vi = tid & 15;          // v column within block

    __shared__ float buf[2][3 * DKK + 17];
    __shared__ float part[256];

    float S[8];
#pragma unroll
    for (int j = 0; j < 8; j++) S[j] = 0.f;

    size_t tbase = (size_t)b * LL;

    float ar = 0.f, ak = 0.f, aw = 0.f, av = 0.f, ac = 0.f;
    {
        size_t tok = tbase;
        if (tid < DKK) {
            ar = r [tok * KD + h * DKK + tid];
            ak = kk[tok * KD + h * DKK + tid];
            aw = ew[tok * KD + h * DKK + tid];
        } else if (tid < DKK + 16) {
            av = v[tok * VD + h * DVV + vb * 16 + (tid - DKK)];
        } else if (tid == DKK + 16) {
            ac = c[tok * NHH + h];
        }
        float* Bn = buf[0];
        if (tid < DKK) {
            Bn[OFF_R + tid] = ar;
            Bn[OFF_K + tid] = ak;
            Bn[OFF_W + tid] = aw;
        } else if (tid < DKK + 16) {
            Bn[OFF_V + (tid - DKK)] = av;
        } else if (tid == DKK + 16) {
            Bn[OFF_C] = ac;
        }
    }
    __syncthreads();

    int pcur = 0;
    for (int t = 0; t < LL; t++) {
        if (t + 1 < LL) {
            size_t tok = tbase + t + 1;
            if (tid < DKK) {
                ar = r [tok * KD + h * DKK + tid];
                ak = kk[tok * KD + h * DKK + tid];
                aw = ew[tok * KD + h * DKK + tid];
            } else if (tid < DKK + 16) {
                av = v[tok * VD + h * DVV + vb * 16 + (tid - DKK)];
            } else if (tid == DKK + 16) {
                ac = c[tok * NHH + h];
            }
        }

        const float* Bc = buf[pcur];
        float p = 0.f;
#pragma unroll
        for (int j = 0; j < 8; j++) p += Bc[OFF_R + kg * 8 + j] * S[j];
        part[kg * 16 + vi] = p;
        __syncthreads();

        if (tid < 16) {
            float s = 0.f;
#pragma unroll
            for (int g = 0; g < 16; g++) s += part[g * 16 + tid];
            s += Bc[OFF_C] * Bc[OFF_V + tid];
            o[(tbase + t) * VD + h * DVV + vb * 16 + tid] = s;
        }
        float vv = Bc[OFF_V + vi];
#pragma unroll
        for (int j = 0; j < 8; j++) {
            S[j] = Bc[OFF_W + kg * 8 + j] * S[j] + Bc[OFF_K + kg * 8 + j] * vv;
        }

        if (t + 1 < LL) {
            float* Bn = buf[pcur ^ 1];
            if (tid < DKK) {
                Bn[OFF_R + tid] = ar;
                Bn[OFF_K + tid] = ak;
                Bn[OFF_W + tid] = aw;
            } else if (tid < DKK + 16) {
                Bn[OFF_V + (tid - DKK)] = av;
            } else if (tid == DKK + 16) {
                Bn[OFF_C] = ac;
            }
        }
        __syncthreads();
        pcur ^= 1;
    }
}

// ---------------- per-head LayerNorm + swish gate -----------------------
__global__ __launch_bounds__(256)
void ln_kernel(const float* __restrict__ o,
               const float* __restrict__ g,
               const float* __restrict__ ln_w,
               const float* __restrict__ ln_b,
               float* __restrict__ og) {
    int th = blockIdx.x;
    int t = th >> 2, h = th & 3;
    int vv = threadIdx.x;
    size_t idx = (size_t)t * VD + h * DVV + vv;
    float val = o[idx];

    __shared__ float rs[8], rs2[8];
    float s1 = val, s2 = val * val;
#pragma unroll
    for (int off = 16; off; off >>= 1) {
        s1 += __shfl_xor_sync(0xffffffffu, s1, off);
        s2 += __shfl_xor_sync(0xffffffffu, s2, off);
    }
    int warp = vv >> 5, lane = vv & 31;
    if (!lane) { rs[warp] = s1; rs2[warp] = s2; }
    __syncthreads();
    float tot = 0.f, tot2 = 0.f;
#pragma unroll
    for (int i = 0; i < 8; i++) { tot += rs[i]; tot2 += rs2[i]; }
    float mean = tot * (1.f / DVV);
    float var = tot2 * (1.f / DVV) - mean * mean;
    float inv = rsqrtf(var + 1e-5f);
    float on = (val - mean) * inv * ln_w[vv] + ln_b[vv];
    float gv = g[idx];
    og[idx] = on * gv * (1.f / (1.f + expf(-gv)));
}

// ---------------- host launcher -----------------------------------------
static float* sym(const void* s) {
    void* p = nullptr;
    cudaGetSymbolAddress(&p, s);
    return (float*)p;
}

static GemmZ5 mk1(const float* A, const float* W, float* C, const float* bias) {
    GemmZ5 d{};
    d.z[0] = GemmZ{A, W, C, bias};
    return d;
}

extern "C" void kernel_launch(void* const* d_in, const int* in_sizes, int n_in,
                              void* d_out, int out_size) {
    const float* x      = (const float*)d_in[0];
    const float* mu_x   = (const float*)d_in[1];
    const float* Wx1    = (const float*)d_in[2];   // [160,1024]
    const float* Wx2    = (const float*)d_in[3];   // [1024,160]
    const float* x_bias = (const float*)d_in[4];   // [5,1024]
    const float* Wr     = (const float*)d_in[5];   // [512,1024]
    const float* Wk     = (const float*)d_in[6];
    const float* Wv     = (const float*)d_in[7];   // [1024,1024]
    const float* Wg     = (const float*)d_in[8];
    const float* Ww1    = (const float*)d_in[9];   // [64,1024]
    const float* Ww2    = (const float*)d_in[10];  // [512,64]
    const float* bw2    = (const float*)d_in[11];  // [512]
    const float* bonus  = (const float*)d_in[12];  // [4,128]
    const float* ln_w   = (const float*)d_in[13];
    const float* ln_b   = (const float*)d_in[14];
    const float* Wo     = (const float*)d_in[15];  // [1024,1024]
    float* out = (float*)d_out;

    float* ax = sym(g_ax); float* xp = sym(g_xp);
    float* am = sym(g_amix);
    float* rb = sym(g_r);  float* kb = sym(g_k);
    float* vb = sym(g_v);  float* gb = sym(g_g);
    float* wd = sym(g_wd); float* ewb = sym(g_ew);
    float* cb = sym(g_c);  float* ob = sym(g_o); float* ogb = sym(g_og);

    dim3 blk128(128);
    dim3 blk256(256);

    // 1. token-shift lerp with mu_x
    ax_kernel<<<(MT * HH + 255) / 256, blk256>>>(x, mu_x, ax);

    // 2. xp = tanh(ax @ Wx1^T)   [4096,160]
    tgemm_kernel<<<dim3(2, 32, 1), blk128>>>(mk1(ax, Wx1, xp, nullptr),
                                             HH, HH, 160, MT, 160, HH,
                                             1, 0, nullptr);

    // 3. fused 5 mixing GEMMs: a_z = x + (xprev-x)*(xp_z@Wx2_z^T + b_z)
    {
        GemmZ5 d{};
        for (int i = 0; i < 5; i++)
            d.z[i] = GemmZ{xp + i * PRR, Wx2 + i * PRR,
                           am + (long)i * MT * HH, x_bias + i * HH};
        tgemm_kernel<<<dim3(8, 32, 5), blk128>>>(d, 160, 160, HH,
                                                 MT, HH, PRR, 0, 1, x);
    }

    // 4a. fused r + k projections
    {
        GemmZ5 d{};
        d.z[0] = GemmZ{am + 0L * MT * HH, Wr, rb, nullptr};
        d.z[1] = GemmZ{am + 2L * MT * HH, Wk, kb, nullptr};
        tgemm_kernel<<<dim3(4, 32, 2), blk128>>>(d, HH, HH, KD,
                                                 MT, KD, HH, 0, 0, nullptr);
    }
    // 4b. fused v + g projections
    {
        GemmZ5 d{};
        d.z[0] = GemmZ{am + 3L * MT * HH, Wv, vb, nullptr};
        d.z[1] = GemmZ{am + 4L * MT * HH, Wg, gb, nullptr};
        tgemm_kernel<<<dim3(8, 32, 2), blk128>>>(d, HH, HH, VD,
                                                 MT, VD, HH, 0, 0, nullptr);
    }
    // 4c. w LoRA: wd = tanh(a1 @ Ww1^T); ew = exp(-exp(wd @ Ww2^T + bw2))
    tgemm_kernel<<<dim3(1, 32, 1), blk128>>>(mk1(am + 1L * MT * HH, Ww1, wd, nullptr),
                                             HH, HH, GRR, MT, GRR, HH,
                                             1, 0, nullptr);
    tgemm_kernel<<<dim3(4, 32, 1), blk128>>>(mk1(wd, Ww2, ewb, bw2),
                                             GRR, GRR, KD, MT, KD, GRR,
                                             0, 2, nullptr);

    // 5. bonus scalar
    c_kernel<<<MT, 128>>>(rb, kb, bonus, cb);

    // 6. recurrence (128 CTAs)
    recur_kernel<<<128, blk256>>>(rb, kb, ewb, vb, cb, ob);

    // 7. LayerNorm + swish gate
    ln_kernel<<<MT * NHH, blk256>>>(ob, gb, ln_w, ln_b, ogb);

    // 8. output projection
    tgemm_kernel<<<dim3(8, 32, 1), blk128>>>(mk1(ogb, Wo, out, nullptr),
                                             VD, VD, HH, MT, HH, VD,
                                             0, 0, nullptr);
}

// round 12
// speedup vs baseline: 1.2855x; 1.2855x over previous
#include <cuda_runtime.h>
#include <cstdint>

// Problem constants
#define BB   2
#define LL   2048
#define HH   1024
#define NHH  4
#define KD   512
#define VD   1024
#define DKK  128
#define DVV  256
#define PRR  32
#define GRR  64
#define MT   4096   // total tokens B*L
#define NPAIR 1024  // LL/2 token pairs per batch

// ---------------- scratch (static __device__, no allocation) ----------------
__device__ float g_ax[MT * HH];          // lerped x with mu_x
__device__ float g_xp[MT * 160];         // tanh proj, 5*PR
__device__ float g_amix[5][MT * HH];     // lerped inputs for r,w,k,v,g
__device__ float g_r [MT * KD];
__device__ float g_k [MT * KD];
__device__ float g_v [MT * VD];
__device__ float g_g [MT * VD];
__device__ float g_wd[MT * GRR];
__device__ float g_ew[MT * KD];          // exp(-exp(w_raw))
__device__ float g_o [MT * VD];          // recurrence output
__device__ float g_og[MT * VD];          // after LN + gate
__device__ float g_prep[BB * NPAIR * NHH * 640];  // fused pair operands
__device__ float g_scal[BB * NPAIR * NHH * 4];    // c0, c1, d per (pair,head)

// ---------------- elementwise: ax = x + (xprev - x)*mu_x ----------------
__global__ void ax_kernel(const float* __restrict__ x,
                          const float* __restrict__ mu_x,
                          float* __restrict__ ax) {
    size_t i = (size_t)blockIdx.x * blockDim.x + threadIdx.x;
    if (i >= (size_t)MT * HH) return;
    int n = (int)(i & (HH - 1));
    size_t m = i >> 10;
    float mu = mu_x[n];
    float xv = x[i];
    float xp = ((m & (LL - 1)) == 0) ? 0.f : x[i - HH];
    ax[i] = xv + (xp - xv) * mu;
}

// ---------------- tf32 tensor-core GEMM (R7 best-measured version) ----------
// C = epi(act(A @ W^T + bias)).  A:[M,K] K-contig, W:[N,K] K-contig.
// CTA tile 128x128, BK=16, 8 warps of 64x32. mma.sync.m16n8k8 tf32.
struct GemmZ  { const float* A; const float* W; float* C; const float* bias; };
struct GemmZ5 { GemmZ z[5]; };

__device__ __forceinline__ uint32_t f2tf32(float v) {
    uint32_t t;
    asm("cvt.rna.tf32.f32 %0, %1;" : "=r"(t) : "f"(v));
    return t;
}

__global__ __launch_bounds__(256, 2)
void tgemm_kernel(GemmZ5 dz, int lda, int ldw, int ldc,
                  int M, int N, int Kdim,
                  int act, int epi,
                  const float* __restrict__ xsrc) {
    const GemmZ gd = dz.z[blockIdx.z];
    const float* A = gd.A;
    const float* W = gd.W;
    float* C = gd.C;
    const float* bias = gd.bias;

    __shared__ float As[2][128][20];   // [m][k], stride 20 -> conflict-free frags
    __shared__ float Bs[2][128][20];   // [n][k]

    int tid = threadIdx.x;
    int mBase = blockIdx.y * 128;
    int nBase = blockIdx.x * 128;
    int lr = tid >> 1;            // 0..127 (row for staging)
    int lc = (tid & 1) * 8;       // 0 or 8 (k-offset for staging)
    int w = tid >> 5, lane = tid & 31;
    int wm = (w >> 2) * 64;       // warp m-offset (0/64)
    int wn = (w & 3) * 32;        // warp n-offset (0/32/64/96)
    int grp = lane >> 2, tig = lane & 3;

    float acc[4][4][4];
#pragma unroll
    for (int mi = 0; mi < 4; mi++)
#pragma unroll
        for (int ni = 0; ni < 4; ni++)
#pragma unroll
            for (int q = 0; q < 4; q++) acc[mi][ni][q] = 0.f;

    int nt = Kdim >> 4;
    int nrow = nBase + lr;
    const float* apBase = A + (size_t)(mBase + lr) * lda + lc;
    const float* wpBase = W + (size_t)nrow * ldw + lc;

    float av[8], bv[8];
    // prologue: tile 0
    {
        const float* ap = apBase;
        *(float4*)(av)     = *(const float4*)(ap);
        *(float4*)(av + 4) = *(const float4*)(ap + 4);
        if (nrow < N) {
            *(float4*)(bv)     = *(const float4*)(wpBase);
            *(float4*)(bv + 4) = *(const float4*)(wpBase + 4);
        } else {
#pragma unroll
            for (int j = 0; j < 8; j++) bv[j] = 0.f;
        }
#pragma unroll
        for (int j = 0; j < 8; j++) {
            As[0][lr][lc + j] = __uint_as_float(f2tf32(av[j]));
            Bs[0][lr][lc + j] = __uint_as_float(f2tf32(bv[j]));
        }
    }
    __syncthreads();

    for (int kt = 0; kt < nt; kt++) {
        int cur = kt & 1;
        bool more = (kt + 1 < nt);
        if (more) {
            const float* ap = apBase + (kt + 1) * 16;
            *(float4*)(av)     = *(const float4*)(ap);
            *(float4*)(av + 4) = *(const float4*)(ap + 4);
            if (nrow < N) {
                const float* wp = wpBase + (kt + 1) * 16;
                *(float4*)(bv)     = *(const float4*)(wp);
                *(float4*)(bv + 4) = *(const float4*)(wp + 4);
            }
        }
#pragma unroll
        for (int k0 = 0; k0 < 16; k0 += 8) {
            uint32_t af[4][4], bf[4][2];
#pragma unroll
            for (int mi = 0; mi < 4; mi++) {
                int r0 = wm + mi * 16 + grp;
                af[mi][0] = __float_as_uint(As[cur][r0][k0 + tig]);
                af[mi][1] = __float_as_uint(As[cur][r0 + 8][k0 + tig]);
                af[mi][2] = __float_as_uint(As[cur][r0][k0 + tig + 4]);
                af[mi][3] = __float_as_uint(As[cur][r0 + 8][k0 + tig + 4]);
            }
#pragma unroll
            for (int ni = 0; ni < 4; ni++) {
                int c0 = wn + ni * 8 + grp;
                bf[ni][0] = __float_as_uint(Bs[cur][c0][k0 + tig]);
                bf[ni][1] = __float_as_uint(Bs[cur][c0][k0 + tig + 4]);
            }
#pragma unroll
            for (int mi = 0; mi < 4; mi++)
#pragma unroll
                for (int ni = 0; ni < 4; ni++) {
                    asm volatile(
                        "mma.sync.aligned.m16n8k8.row.col.f32.tf32.tf32.f32 "
                        "{%0,%1,%2,%3}, {%4,%5,%6,%7}, {%8,%9}, {%0,%1,%2,%3};"
                        : "+f"(acc[mi][ni][0]), "+f"(acc[mi][ni][1]),
                          "+f"(acc[mi][ni][2]), "+f"(acc[mi][ni][3])
                        : "r"(af[mi][0]), "r"(af[mi][1]),
                          "r"(af[mi][2]), "r"(af[mi][3]),
                          "r"(bf[ni][0]), "r"(bf[ni][1]));
                }
        }
        if (more) {
            int nxt = cur ^ 1;
#pragma unroll
            for (int j = 0; j < 8; j++) {
                As[nxt][lr][lc + j] = __uint_as_float(f2tf32(av[j]));
                Bs[nxt][lr][lc + j] = __uint_as_float(f2tf32(bv[j]));
            }
        }
        __syncthreads();
    }

    // epilogue: float2-vectorized
#pragma unroll
    for (int mi = 0; mi < 4; mi++) {
#pragma unroll
        for (int ni = 0; ni < 4; ni++) {
            int m0 = mBase + wm + mi * 16 + grp;
            int n0 = nBase + wn + ni * 8 + tig * 2;
            if (n0 >= N) continue;
#pragma unroll
            for (int hr = 0; hr < 2; hr++) {
                int m = m0 + hr * 8;
                float vx = acc[mi][ni][hr * 2 + 0];
                float vy = acc[mi][ni][hr * 2 + 1];
                if (bias) { vx += bias[n0]; vy += bias[n0 + 1]; }
                if (act)  { vx = tanhf(vx); vy = tanhf(vy); }
                if (epi == 1) {
                    float2 xv = *(const float2*)&xsrc[(size_t)m * HH + n0];
                    float2 xp = ((m & (LL - 1)) == 0) ? make_float2(0.f, 0.f)
                              : *(const float2*)&xsrc[(size_t)(m - 1) * HH + n0];
                    vx = xv.x + (xp.x - xv.x) * vx;
                    vy = xv.y + (xp.y - xv.y) * vy;
                } else if (epi == 2) {
                    vx = expf(-expf(vx));
                    vy = expf(-expf(vy));
                }
                *(float2*)&C[(size_t)m * ldc + n0] = make_float2(vx, vy);
            }
        }
    }
}

// ---------------- pair-fusion prep: fused operands for 2-token steps -------
// For pair (t0=2u, t1=2u+1) of chain (b,h):
//   prep[0]=r0, prep[1]=r1*ew0, prep[2]=ew1*ew0, prep[3]=ew1*k0, prep[4]=k1
//   scal = { c0 = r0·bonus·k0,  c1 = r1·bonus·k1,  d = r1·k0 }
__global__ __launch_bounds__(128)
void prep_kernel(const float* __restrict__ r,
                 const float* __restrict__ k,
                 const float* __restrict__ ew,
                 const float* __restrict__ bonus,
                 float* __restrict__ prep,
                 float* __restrict__ scal) {
    int blk = blockIdx.x;            // ((b*NPAIR+u)*NHH + h)
    int h = blk & 3;
    int bu = blk >> 2;
    int b = bu >> 10, u = bu & (NPAIR - 1);
    int t0 = b * LL + 2 * u;
    int kk = threadIdx.x;
    size_t i0 = (size_t)t0 * KD + h * DKK + kk;
    size_t i1 = i0 + KD;
    float r0 = r[i0], r1 = r[i1];
    float k0 = k[i0], k1 = k[i1];
    float e0 = ew[i0], e1 = ew[i1];
    float bo = bonus[h * DKK + kk];

    float* pp = prep + (size_t)blk * 640;
    pp[kk]       = r0;
    pp[128 + kk] = r1 * e0;
    pp[256 + kk] = e1 * e0;
    pp[384 + kk] = e1 * k0;
    pp[512 + kk] = k1;

    float c0 = r0 * bo * k0;
    float c1 = r1 * bo * k1;
    float d  = r1 * k0;
#pragma unroll
    for (int off = 16; off; off >>= 1) {
        c0 += __shfl_xor_sync(0xffffffffu, c0, off);
        c1 += __shfl_xor_sync(0xffffffffu, c1, off);
        d  += __shfl_xor_sync(0xffffffffu, d, off);
    }
    __shared__ float sc[3][4];
    int warp = kk >> 5, lane = kk & 31;
    if (!lane) { sc[0][warp] = c0; sc[1][warp] = c1; sc[2][warp] = d; }
    __syncthreads();
    if (kk == 0) {
        float* sp = scal + (size_t)blk * 4;
        sp[0] = sc[0][0] + sc[0][1] + sc[0][2] + sc[0][3];
        sp[1] = sc[1][0] + sc[1][1] + sc[1][2] + sc[1][3];
        sp[2] = sc[2][0] + sc[2][1] + sc[2][2] + sc[2][3];
    }
}

// ---------------- 2-token sequential recurrence (128 CTAs) -----------------
// 16 CTAs per chain, 16 v-cols each. kg=tid/16 owns 8 k, vi=tid%16.
// Per iteration handles a token PAIR: 2 barriers instead of 4.
#define RP_V 640
#define RP_S 672
__global__ __launch_bounds__(256)
void recur2_kernel(const float* __restrict__ prep,
                   const float* __restrict__ scal,
                   const float* __restrict__ v,
                   float* __restrict__ o) {
    int blk = blockIdx.x;
    int chain = blk >> 4;       // b*4+h
    int vb = blk & 15;
    int b = chain >> 2, h = chain & 3;
    int tid = threadIdx.x;
    int kg = tid >> 4;          // 0..15
    int vi = tid & 15;

    __shared__ float buf[2][676];
    __shared__ float part1[256], part2[256];

    float S[8];
#pragma unroll
    for (int j = 0; j < 8; j++) S[j] = 0.f;

    size_t chainBase = ((size_t)b * NPAIR) * 4 + h;   // +4*u per pair
    size_t tb = (size_t)b * LL;

    float pf0 = 0.f, pf1 = 0.f, pf2 = 0.f, pv = 0.f, ps = 0.f;

    // prologue: load pair 0
    {
        size_t pb = (chainBase) * 640;
        pf0 = prep[pb + tid];
        pf1 = prep[pb + tid + 256];
        if (tid < 128) pf2 = prep[pb + tid + 512];
        if (tid >= 128 && tid < 160) {
            int j = tid - 128;
            size_t t = tb + (j >> 4);           // token 0 or 1
            pv = v[t * VD + h * DVV + vb * 16 + (j & 15)];
        }
        if (tid >= 160 && tid < 163) ps = scal[chainBase * 4 + (tid - 160)];
        float* Bn = buf[0];
        Bn[tid] = pf0;
        Bn[256 + tid] = pf1;
        if (tid < 128) Bn[512 + tid] = pf2;
        if (tid >= 128 && tid < 160) Bn[RP_V + tid - 128] = pv;
        if (tid >= 160 && tid < 163) Bn[RP_S + tid - 160] = ps;
    }
    __syncthreads();

    int pcur = 0;
    for (int u = 0; u < NPAIR; u++) {
        // prefetch pair u+1
        if (u + 1 < NPAIR) {
            size_t pb = (chainBase + 4 * (u + 1)) * 640;
            pf0 = prep[pb + tid];
            pf1 = prep[pb + tid + 256];
            if (tid < 128) pf2 = prep[pb + tid + 512];
            if (tid >= 128 && tid < 160) {
                int j = tid - 128;
                size_t t = tb + 2 * (u + 1) + (j >> 4);
                pv = v[t * VD + h * DVV + vb * 16 + (j & 15)];
            }
            if (tid >= 160 && tid < 163)
                ps = scal[(chainBase + 4 * (u + 1)) * 4 + (tid - 160)];
        }

        const float* Bc = buf[pcur];
        // o partials for both tokens of the pair
        float p1 = 0.f, p2 = 0.f;
#pragma unroll
        for (int j = 0; j < 8; j++) {
            int idx = kg * 8 + j;
            p1 += Bc[idx] * S[j];           // rA  = r0
            p2 += Bc[128 + idx] * S[j];     // rB  = r1*ew0
        }
        part1[kg * 16 + vi] = p1;
        part2[kg * 16 + vi] = p2;
        __syncthreads();

        if (tid < 16) {
            float s0 = 0.f, s1 = 0.f;
#pragma unroll
            for (int g = 0; g < 16; g++) {
                s0 += part1[g * 16 + tid];
                s1 += part2[g * 16 + tid];
            }
            float v0 = Bc[RP_V + tid], v1 = Bc[RP_V + 16 + tid];
            float c0 = Bc[RP_S], c1 = Bc[RP_S + 1], dd = Bc[RP_S + 2];
            size_t t0 = tb + 2 * u;
            o[t0 * VD + h * DVV + vb * 16 + tid] = s0 + c0 * v0;
            o[(t0 + 1) * VD + h * DVV + vb * 16 + tid] = s1 + dd * v0 + c1 * v1;
        }

        // state update over the pair: S = wP*S + kA*v0 + kB*v1
        float v0 = Bc[RP_V + vi], v1 = Bc[RP_V + 16 + vi];
#pragma unroll
        for (int j = 0; j < 8; j++) {
            int idx = kg * 8 + j;
            S[j] = Bc[256 + idx] * S[j] + Bc[384 + idx] * v0 + Bc[512 + idx] * v1;
        }

        // stage prefetched pair
        if (u + 1 < NPAIR) {
            float* Bn = buf[pcur ^ 1];
            Bn[tid] = pf0;
            Bn[256 + tid] = pf1;
            if (tid < 128) Bn[512 + tid] = pf2;
            if (tid >= 128 && tid < 160) Bn[RP_V + tid - 128] = pv;
            if (tid >= 160 && tid < 163) Bn[RP_S + tid - 160] = ps;
        }
        __syncthreads();
        pcur ^= 1;
    }
}

// ---------------- per-head LayerNorm + swish gate -----------------------
__global__ __launch_bounds__(256)
void ln_kernel(const float* __restrict__ o,
               const float* __restrict__ g,
               const float* __restrict__ ln_w,
               const float* __restrict__ ln_b,
               float* __restrict__ og) {
    int th = blockIdx.x;
    int t = th >> 2, h = th & 3;
    int vv = threadIdx.x;
    size_t idx = (size_t)t * VD + h * DVV + vv;
    float val = o[idx];

    __shared__ float rs[8], rs2[8];
    float s1 = val, s2 = val * val;
#pragma unroll
    for (int off = 16; off; off >>= 1) {
        s1 += __shfl_xor_sync(0xffffffffu, s1, off);
        s2 += __shfl_xor_sync(0xffffffffu, s2, off);
    }
    int warp = vv >> 5, lane = vv & 31;
    if (!lane) { rs[warp] = s1; rs2[warp] = s2; }
    __syncthreads();
    float tot = 0.f, tot2 = 0.f;
#pragma unroll
    for (int i = 0; i < 8; i++) { tot += rs[i]; tot2 += rs2[i]; }
    float mean = tot * (1.f / DVV);
    float var = tot2 * (1.f / DVV) - mean * mean;
    float inv = rsqrtf(var + 1e-5f);
    float on = (val - mean) * inv * ln_w[vv] + ln_b[vv];
    float gv = g[idx];
    og[idx] = on * gv * (1.f / (1.f + expf(-gv)));
}

// ---------------- host launcher -----------------------------------------
static float* sym(const void* s) {
    void* p = nullptr;
    cudaGetSymbolAddress(&p, s);
    return (float*)p;
}

static GemmZ5 mk1(const float* A, const float* W, float* C, const float* bias) {
    GemmZ5 d{};
    d.z[0] = GemmZ{A, W, C, bias};
    return d;
}

extern "C" void kernel_launch(void* const* d_in, const int* in_sizes, int n_in,
                              void* d_out, int out_size) {
    const float* x      = (const float*)d_in[0];
    const float* mu_x   = (const float*)d_in[1];
    const float* Wx1    = (const float*)d_in[2];   // [160,1024]
    const float* Wx2    = (const float*)d_in[3];   // [1024,160]
    const float* x_bias = (const float*)d_in[4];   // [5,1024]
    const float* Wr     = (const float*)d_in[5];   // [512,1024]
    const float* Wk     = (const float*)d_in[6];
    const float* Wv     = (const float*)d_in[7];   // [1024,1024]
    const float* Wg     = (const float*)d_in[8];
    const float* Ww1    = (const float*)d_in[9];   // [64,1024]
    const float* Ww2    = (const float*)d_in[10];  // [512,64]
    const float* bw2    = (const float*)d_in[11];  // [512]
    const float* bonus  = (const float*)d_in[12];  // [4,128]
    const float* ln_w   = (const float*)d_in[13];
    const float* ln_b   = (const float*)d_in[14];
    const float* Wo     = (const float*)d_in[15];  // [1024,1024]
    float* out = (float*)d_out;

    float* ax = sym(g_ax); float* xp = sym(g_xp);
    float* am = sym(g_amix);
    float* rb = sym(g_r);  float* kb = sym(g_k);
    float* vb = sym(g_v);  float* gb = sym(g_g);
    float* wd = sym(g_wd); float* ewb = sym(g_ew);
    float* ob = sym(g_o);  float* ogb = sym(g_og);
    float* pb = sym(g_prep); float* sb = sym(g_scal);

    dim3 blk128(128);
    dim3 blk256(256);

    // 1. token-shift lerp with mu_x
    ax_kernel<<<(MT * HH + 255) / 256, blk256>>>(x, mu_x, ax);

    // 2. xp = tanh(ax @ Wx1^T)   [4096,160]
    tgemm_kernel<<<dim3(2, 32, 1), blk256>>>(mk1(ax, Wx1, xp, nullptr),
                                             HH, HH, 160, MT, 160, HH,
                                             1, 0, nullptr);

    // 3. fused 5 mixing GEMMs: a_z = x + (xprev-x)*(xp_z@Wx2_z^T + b_z)
    {
        GemmZ5 d{};
        for (int i = 0; i < 5; i++)
            d.z[i] = GemmZ{xp + i * PRR, Wx2 + i * PRR,
                           am + (long)i * MT * HH, x_bias + i * HH};
        tgemm_kernel<<<dim3(8, 32, 5), blk256>>>(d, 160, 160, HH,
                                                 MT, HH, PRR, 0, 1, x);
    }

    // 4a. fused r + k projections
    {
        GemmZ5 d{};
        d.z[0] = GemmZ{am + 0L * MT * HH, Wr, rb, nullptr};
        d.z[1] = GemmZ{am + 2L * MT * HH, Wk, kb, nullptr};
        tgemm_kernel<<<dim3(4, 32, 2), blk256>>>(d, HH, HH, KD,
                                                 MT, KD, HH, 0, 0, nullptr);
    }
    // 4b. fused v + g projections
    {
        GemmZ5 d{};
        d.z[0] = GemmZ{am + 3L * MT * HH, Wv, vb, nullptr};
        d.z[1] = GemmZ{am + 4L * MT * HH, Wg, gb, nullptr};
        tgemm_kernel<<<dim3(8, 32, 2), blk256>>>(d, HH, HH, VD,
                                                 MT, VD, HH, 0, 0, nullptr);
    }
    // 4c. w LoRA: wd = tanh(a1 @ Ww1^T); ew = exp(-exp(wd @ Ww2^T + bw2))
    tgemm_kernel<<<dim3(1, 32, 1), blk256>>>(mk1(am + 1L * MT * HH, Ww1, wd, nullptr),
                                             HH, HH, GRR, MT, GRR, HH,
                                             1, 0, nullptr);
    tgemm_kernel<<<dim3(4, 32, 1), blk256>>>(mk1(wd, Ww2, ewb, bw2),
                                             GRR, GRR, KD, MT, KD, GRR,
                                             0, 2, nullptr);

    // 5. pair-fusion prep (absorbs bonus-scalar kernel)
    prep_kernel<<<BB * NPAIR * NHH, blk128>>>(rb, kb, ewb, bonus, pb, sb);

    // 6. 2-token recurrence (128 CTAs, 1024 sequential iterations)
    recur2_kernel<<<128, blk256>>>(pb, sb, vb, ob);

    // 7. LayerNorm + swish gate
    ln_kernel<<<MT * NHH, blk256>>>(ob, gb, ln_w, ln_b, ogb);

    // 8. output projection
    tgemm_kernel<<<dim3(8, 32, 1), blk256>>>(mk1(ogb, Wo, out, nullptr),
                                             VD, VD, HH, MT, HH, VD,
                                             0, 0, nullptr);
}

// round 15
// speedup vs baseline: 1.6539x; 1.2866x over previous
#include <cuda_runtime.h>
#include <cstdint>

// Problem constants
#define BB   2
#define LL   2048
#define HH   1024
#define NHH  4
#define KD   512
#define VD   1024
#define DKK  128
#define DVV  256
#define PRR  32
#define GRR  64
#define MT   4096   // total tokens B*L
#define NQUAD 512   // LL/4 token quads per batch

// ---------------- scratch (static __device__, no allocation) ----------------
__device__ float g_ax[MT * HH];          // lerped x with mu_x
__device__ float g_xp[MT * 160];         // tanh proj, 5*PR
__device__ float g_amix[5][MT * HH];     // lerped inputs for r,w,k,v,g
__device__ float g_r [MT * KD];
__device__ float g_k [MT * KD];
__device__ float g_v [MT * VD];
__device__ float g_g [MT * VD];
__device__ float g_wd[MT * GRR];
__device__ float g_ew[MT * KD];          // exp(-exp(w_raw))
__device__ float g_o [MT * VD];          // recurrence output
__device__ float g_og[MT * VD];          // after LN + gate
__device__ float g_prep[BB * NQUAD * NHH * 1152];  // fused quad operands
__device__ float g_scal[BB * NQUAD * NHH * 12];    // c0..c3, d10,d20,d21,d30,d31,d32

// ---------------- elementwise: ax = x + (xprev - x)*mu_x ----------------
__global__ void ax_kernel(const float* __restrict__ x,
                          const float* __restrict__ mu_x,
                          float* __restrict__ ax) {
    size_t i = (size_t)blockIdx.x * blockDim.x + threadIdx.x;
    if (i >= (size_t)MT * HH) return;
    int n = (int)(i & (HH - 1));
    size_t m = i >> 10;
    float mu = mu_x[n];
    float xv = x[i];
    float xp = ((m & (LL - 1)) == 0) ? 0.f : x[i - HH];
    ax[i] = xv + (xp - xv) * mu;
}

// ---------------- tf32 tensor-core GEMM (best-measured version) -------------
struct GemmZ  { const float* A; const float* W; float* C; const float* bias; };
struct GemmZ5 { GemmZ z[5]; };

__device__ __forceinline__ uint32_t f2tf32(float v) {
    uint32_t t;
    asm("cvt.rna.tf32.f32 %0, %1;" : "=r"(t) : "f"(v));
    return t;
}

__global__ __launch_bounds__(256, 2)
void tgemm_kernel(GemmZ5 dz, int lda, int ldw, int ldc,
                  int M, int N, int Kdim,
                  int act, int epi,
                  const float* __restrict__ xsrc) {
    const GemmZ gd = dz.z[blockIdx.z];
    const float* A = gd.A;
    const float* W = gd.W;
    float* C = gd.C;
    const float* bias = gd.bias;

    __shared__ float As[2][128][20];
    __shared__ float Bs[2][128][20];

    int tid = threadIdx.x;
    int mBase = blockIdx.y * 128;
    int nBase = blockIdx.x * 128;
    int lr = tid >> 1;
    int lc = (tid & 1) * 8;
    int w = tid >> 5, lane = tid & 31;
    int wm = (w >> 2) * 64;
    int wn = (w & 3) * 32;
    int grp = lane >> 2, tig = lane & 3;

    float acc[4][4][4];
#pragma unroll
    for (int mi = 0; mi < 4; mi++)
#pragma unroll
        for (int ni = 0; ni < 4; ni++)
#pragma unroll
            for (int q = 0; q < 4; q++) acc[mi][ni][q] = 0.f;

    int nt = Kdim >> 4;
    int nrow = nBase + lr;
    const float* apBase = A + (size_t)(mBase + lr) * lda + lc;
    const float* wpBase = W + (size_t)nrow * ldw + lc;

    float av[8], bv[8];
    {
        const float* ap = apBase;
        *(float4*)(av)     = *(const float4*)(ap);
        *(float4*)(av + 4) = *(const float4*)(ap + 4);
        if (nrow < N) {
            *(float4*)(bv)     = *(const float4*)(wpBase);
            *(float4*)(bv + 4) = *(const float4*)(wpBase + 4);
        } else {
#pragma unroll
            for (int j = 0; j < 8; j++) bv[j] = 0.f;
        }
#pragma unroll
        for (int j = 0; j < 8; j++) {
            As[0][lr][lc + j] = __uint_as_float(f2tf32(av[j]));
            Bs[0][lr][lc + j] = __uint_as_float(f2tf32(bv[j]));
        }
    }
    __syncthreads();

    for (int kt = 0; kt < nt; kt++) {
        int cur = kt & 1;
        bool more = (kt + 1 < nt);
        if (more) {
            const float* ap = apBase + (kt + 1) * 16;
            *(float4*)(av)     = *(const float4*)(ap);
            *(float4*)(av + 4) = *(const float4*)(ap + 4);
            if (nrow < N) {
                const float* wp = wpBase + (kt + 1) * 16;
                *(float4*)(bv)     = *(const float4*)(wp);
                *(float4*)(bv + 4) = *(const float4*)(wp + 4);
            }
        }
#pragma unroll
        for (int k0 = 0; k0 < 16; k0 += 8) {
            uint32_t af[4][4], bf[4][2];
#pragma unroll
            for (int mi = 0; mi < 4; mi++) {
                int r0 = wm + mi * 16 + grp;
                af[mi][0] = __float_as_uint(As[cur][r0][k0 + tig]);
                af[mi][1] = __float_as_uint(As[cur][r0 + 8][k0 + tig]);
                af[mi][2] = __float_as_uint(As[cur][r0][k0 + tig + 4]);
                af[mi][3] = __float_as_uint(As[cur][r0 + 8][k0 + tig + 4]);
            }
#pragma unroll
            for (int ni = 0; ni < 4; ni++) {
                int c0 = wn + ni * 8 + grp;
                bf[ni][0] = __float_as_uint(Bs[cur][c0][k0 + tig]);
                bf[ni][1] = __float_as_uint(Bs[cur][c0][k0 + tig + 4]);
            }
#pragma unroll
            for (int mi = 0; mi < 4; mi++)
#pragma unroll
                for (int ni = 0; ni < 4; ni++) {
                    asm volatile(
                        "mma.sync.aligned.m16n8k8.row.col.f32.tf32.tf32.f32 "
                        "{%0,%1,%2,%3}, {%4,%5,%6,%7}, {%8,%9}, {%0,%1,%2,%3};"
                        : "+f"(acc[mi][ni][0]), "+f"(acc[mi][ni][1]),
                          "+f"(acc[mi][ni][2]), "+f"(acc[mi][ni][3])
                        : "r"(af[mi][0]), "r"(af[mi][1]),
                          "r"(af[mi][2]), "r"(af[mi][3]),
                          "r"(bf[ni][0]), "r"(bf[ni][1]));
                }
        }
        if (more) {
            int nxt = cur ^ 1;
#pragma unroll
            for (int j = 0; j < 8; j++) {
                As[nxt][lr][lc + j] = __uint_as_float(f2tf32(av[j]));
                Bs[nxt][lr][lc + j] = __uint_as_float(f2tf32(bv[j]));
            }
        }
        __syncthreads();
    }

#pragma unroll
    for (int mi = 0; mi < 4; mi++) {
#pragma unroll
        for (int ni = 0; ni < 4; ni++) {
            int m0 = mBase + wm + mi * 16 + grp;
            int n0 = nBase + wn + ni * 8 + tig * 2;
            if (n0 >= N) continue;
#pragma unroll
            for (int hr = 0; hr < 2; hr++) {
                int m = m0 + hr * 8;
                float vx = acc[mi][ni][hr * 2 + 0];
                float vy = acc[mi][ni][hr * 2 + 1];
                if (bias) { vx += bias[n0]; vy += bias[n0 + 1]; }
                if (act)  { vx = tanhf(vx); vy = tanhf(vy); }
                if (epi == 1) {
                    float2 xv = *(const float2*)&xsrc[(size_t)m * HH + n0];
                    float2 xp = ((m & (LL - 1)) == 0) ? make_float2(0.f, 0.f)
                              : *(const float2*)&xsrc[(size_t)(m - 1) * HH + n0];
                    vx = xv.x + (xp.x - xv.x) * vx;
                    vy = xv.y + (xp.y - xv.y) * vy;
                } else if (epi == 2) {
                    vx = expf(-expf(vx));
                    vy = expf(-expf(vy));
                }
                *(float2*)&C[(size_t)m * ldc + n0] = make_float2(vx, vy);
            }
        }
    }
}

// ---------------- quad-fusion prep: fused operands for 4-token chunks ------
// a_t = r_t * prod_{j<t} e_j ; W = prod e_j ; b_s = (prod_{j>s} e_j) * k_s
// scalars: c_t = r_t·bonus·k_t ; d_{t,s} = (r_t * prod_{s<j<t} e_j)·k_s
__global__ __launch_bounds__(128)
void prep4_kernel(const float* __restrict__ r,
                  const float* __restrict__ k,
                  const float* __restrict__ ew,
                  const float* __restrict__ bonus,
                  float* __restrict__ prep,
                  float* __restrict__ scal) {
    int blk = blockIdx.x;            // ((b*NQUAD+u)*NHH + h)
    int h = blk & 3;
    int bu = blk >> 2;
    int b = bu >> 9, u = bu & (NQUAD - 1);
    int t0 = b * LL + 4 * u;
    int kk = threadIdx.x;
    size_t i0 = (size_t)t0 * KD + h * DKK + kk;
    float r0 = r[i0],          k0 = k[i0],          e0 = ew[i0];
    float r1 = r[i0 + KD],     k1 = k[i0 + KD],     e1 = ew[i0 + KD];
    float r2 = r[i0 + 2 * KD], k2 = k[i0 + 2 * KD], e2 = ew[i0 + 2 * KD];
    float r3 = r[i0 + 3 * KD], k3 = k[i0 + 3 * KD], e3 = ew[i0 + 3 * KD];
    float bo = bonus[h * DKK + kk];

    float p10 = e1 * e0;
    float p210 = e2 * p10;
    float Wp = e3 * p210;
    float s32 = e3 * e2;
    float s321 = s32 * e1;

    float* pp = prep + (size_t)blk * 1152;
    pp[kk]          = r0;
    pp[128 + kk]    = r1 * e0;
    pp[256 + kk]    = r2 * p10;
    pp[384 + kk]    = r3 * p210;
    pp[512 + kk]    = Wp;
    pp[640 + kk]    = k0 * s321;
    pp[768 + kk]    = k1 * s32;
    pp[896 + kk]    = k2 * e3;
    pp[1024 + kk]   = k3;

    float vals[10];
    vals[0] = r0 * bo * k0;
    vals[1] = r1 * bo * k1;
    vals[2] = r2 * bo * k2;
    vals[3] = r3 * bo * k3;
    vals[4] = r1 * k0;               // d10
    vals[5] = r2 * e1 * k0;          // d20
    vals[6] = r2 * k1;               // d21
    vals[7] = r3 * e2 * e1 * k0;     // d30
    vals[8] = r3 * e2 * k1;          // d31
    vals[9] = r3 * k2;               // d32

#pragma unroll
    for (int i = 0; i < 10; i++) {
        float s = vals[i];
#pragma unroll
        for (int off = 16; off; off >>= 1) s += __shfl_xor_sync(0xffffffffu, s, off);
        vals[i] = s;
    }
    __shared__ float sc[10][4];
    int warp = kk >> 5, lane = kk & 31;
    if (!lane) {
#pragma unroll
        for (int i = 0; i < 10; i++) sc[i][warp] = vals[i];
    }
    __syncthreads();
    if (kk < 10) {
        scal[(size_t)blk * 12 + kk] =
            sc[kk][0] + sc[kk][1] + sc[kk][2] + sc[kk][3];
    }
}

// ---------------- 4-token sequential recurrence (128 CTAs) -----------------
// 16 CTAs per chain, 16 v-cols each. kg=tid/16 owns 8 k, vi=tid%16.
// Per iteration handles a 4-token chunk: 2 barriers per 4 tokens.
#define QV 1152
#define QS 1216
__global__ __launch_bounds__(256)
void recur4_kernel(const float* __restrict__ prep,
                   const float* __restrict__ scal,
                   const float* __restrict__ v,
                   float* __restrict__ o) {
    int blk = blockIdx.x;
    int chain = blk >> 4;       // b*4+h
    int vb = blk & 15;
    int b = chain >> 2, h = chain & 3;
    int tid = threadIdx.x;
    int kg = tid >> 4;          // 0..15
    int vi = tid & 15;

    __shared__ float buf[2][1228];
    __shared__ float part[4][272];   // stride 17 -> conflict-free reduce

    float S[8];
#pragma unroll
    for (int j = 0; j < 8; j++) S[j] = 0.f;

    size_t tb = (size_t)b * LL;
    size_t qBase = ((size_t)b * NQUAD) * 4 + h;   // prep/scal block index; +4 per quad

    float pf0 = 0.f, pf1 = 0.f, pf2 = 0.f, pf3 = 0.f, pf4 = 0.f, pv = 0.f, ps = 0.f;

    // prologue: load quad 0
    {
        size_t pb = qBase * 1152;
        pf0 = prep[pb + tid];
        pf1 = prep[pb + 256 + tid];
        pf2 = prep[pb + 512 + tid];
        pf3 = prep[pb + 768 + tid];
        if (tid < 128) pf4 = prep[pb + 1024 + tid];
        if (tid >= 128 && tid < 192) {
            int j = tid - 128;
            pv = v[(tb + (j >> 4)) * VD + h * DVV + vb * 16 + (j & 15)];
        }
        if (tid >= 192 && tid < 202) ps = scal[qBase * 12 + (tid - 192)];
        float* Bn = buf[0];
        Bn[tid] = pf0; Bn[256 + tid] = pf1; Bn[512 + tid] = pf2; Bn[768 + tid] = pf3;
        if (tid < 128) Bn[1024 + tid] = pf4;
        if (tid >= 128 && tid < 192) Bn[QV + tid - 128] = pv;
        if (tid >= 192 && tid < 202) Bn[QS + tid - 192] = ps;
    }
    __syncthreads();

    int pcur = 0;
    for (int u = 0; u < NQUAD; u++) {
        // prefetch quad u+1
        if (u + 1 < NQUAD) {
            size_t pb = (qBase + 4 * (u + 1)) * 1152;
            pf0 = prep[pb + tid];
            pf1 = prep[pb + 256 + tid];
            pf2 = prep[pb + 512 + tid];
            pf3 = prep[pb + 768 + tid];
            if (tid < 128) pf4 = prep[pb + 1024 + tid];
            if (tid >= 128 && tid < 192) {
                int j = tid - 128;
                pv = v[(tb + 4 * (u + 1) + (j >> 4)) * VD + h * DVV + vb * 16 + (j & 15)];
            }
            if (tid >= 192 && tid < 202)
                ps = scal[(qBase + 4 * (u + 1)) * 12 + (tid - 192)];
        }

        const float* Bc = buf[pcur];
        // o partials for all 4 tokens
        float p0 = 0.f, p1 = 0.f, p2 = 0.f, p3 = 0.f;
#pragma unroll
        for (int j = 0; j < 8; j++) {
            int idx = kg * 8 + j;
            float sj = S[j];
            p0 += Bc[idx] * sj;
            p1 += Bc[128 + idx] * sj;
            p2 += Bc[256 + idx] * sj;
            p3 += Bc[384 + idx] * sj;
        }
        int pidx = kg * 17 + vi;
        part[0][pidx] = p0; part[1][pidx] = p1;
        part[2][pidx] = p2; part[3][pidx] = p3;
        __syncthreads();

        if (tid < 64) {
            int tv = tid >> 4, col = tid & 15;
            float s = 0.f;
#pragma unroll
            for (int g = 0; g < 16; g++) s += part[tv][g * 17 + col];
            float v0 = Bc[QV + col], v1 = Bc[QV + 16 + col];
            float v2 = Bc[QV + 32 + col], v3 = Bc[QV + 48 + col];
            float ov;
            if (tv == 0) {
                ov = s + Bc[QS + 0] * v0;
            } else if (tv == 1) {
                ov = s + Bc[QS + 4] * v0 + Bc[QS + 1] * v1;
            } else if (tv == 2) {
                ov = s + Bc[QS + 5] * v0 + Bc[QS + 6] * v1 + Bc[QS + 2] * v2;
            } else {
                ov = s + Bc[QS + 7] * v0 + Bc[QS + 8] * v1
                       + Bc[QS + 9] * v2 + Bc[QS + 3] * v3;
            }
            o[(tb + 4 * u + tv) * VD + h * DVV + vb * 16 + col] = ov;
        }

        // state update: S = W*S + b0*v0 + b1*v1 + b2*v2 + b3*v3
        float v0 = Bc[QV + vi], v1 = Bc[QV + 16 + vi];
        float v2 = Bc[QV + 32 + vi], v3 = Bc[QV + 48 + vi];
#pragma unroll
        for (int j = 0; j < 8; j++) {
            int idx = kg * 8 + j;
            S[j] = Bc[512 + idx] * S[j] + Bc[640 + idx] * v0 + Bc[768 + idx] * v1
                 + Bc[896 + idx] * v2 + Bc[1024 + idx] * v3;
        }

        // stage prefetched quad
        if (u + 1 < NQUAD) {
            float* Bn = buf[pcur ^ 1];
            Bn[tid] = pf0; Bn[256 + tid] = pf1; Bn[512 + tid] = pf2; Bn[768 + tid] = pf3;
            if (tid < 128) Bn[1024 + tid] = pf4;
            if (tid >= 128 && tid < 192) Bn[QV + tid - 128] = pv;
            if (tid >= 192 && tid < 202) Bn[QS + tid - 192] = ps;
        }
        __syncthreads();
        pcur ^= 1;
    }
}

// ---------------- per-head LayerNorm + swish gate -----------------------
__global__ __launch_bounds__(256)
void ln_kernel(const float* __restrict__ o,
               const float* __restrict__ g,
               const float* __restrict__ ln_w,
               const float* __restrict__ ln_b,
               float* __restrict__ og) {
    int th = blockIdx.x;
    int t = th >> 2, h = th & 3;
    int vv = threadIdx.x;
    size_t idx = (size_t)t * VD + h * DVV + vv;
    float val = o[idx];

    __shared__ float rs[8], rs2[8];
    float s1 = val, s2 = val * val;
#pragma unroll
    for (int off = 16; off; off >>= 1) {
        s1 += __shfl_xor_sync(0xffffffffu, s1, off);
        s2 += __shfl_xor_sync(0xffffffffu, s2, off);
    }
    int warp = vv >> 5, lane = vv & 31;
    if (!lane) { rs[warp] = s1; rs2[warp] = s2; }
    __syncthreads();
    float tot = 0.f, tot2 = 0.f;
#pragma unroll
    for (int i = 0; i < 8; i++) { tot += rs[i]; tot2 += rs2[i]; }
    float mean = tot * (1.f / DVV);
    float var = tot2 * (1.f / DVV) - mean * mean;
    float inv = rsqrtf(var + 1e-5f);
    float on = (val - mean) * inv * ln_w[vv] + ln_b[vv];
    float gv = g[idx];
    og[idx] = on * gv * (1.f / (1.f + expf(-gv)));
}

// ---------------- host launcher -----------------------------------------
static float* sym(const void* s) {
    void* p = nullptr;
    cudaGetSymbolAddress(&p, s);
    return (float*)p;
}

static GemmZ5 mk1(const float* A, const float* W, float* C, const float* bias) {
    GemmZ5 d{};
    d.z[0] = GemmZ{A, W, C, bias};
    return d;
}

extern "C" void kernel_launch(void* const* d_in, const int* in_sizes, int n_in,
                              void* d_out, int out_size) {
    const float* x      = (const float*)d_in[0];
    const float* mu_x   = (const float*)d_in[1];
    const float* Wx1    = (const float*)d_in[2];   // [160,1024]
    const float* Wx2    = (const float*)d_in[3];   // [1024,160]
    const float* x_bias = (const float*)d_in[4];   // [5,1024]
    const float* Wr     = (const float*)d_in[5];   // [512,1024]
    const float* Wk     = (const float*)d_in[6];
    const float* Wv     = (const float*)d_in[7];   // [1024,1024]
    const float* Wg     = (const float*)d_in[8];
    const float* Ww1    = (const float*)d_in[9];   // [64,1024]
    const float* Ww2    = (const float*)d_in[10];  // [512,64]
    const float* bw2    = (const float*)d_in[11];  // [512]
    const float* bonus  = (const float*)d_in[12];  // [4,128]
    const float* ln_w   = (const float*)d_in[13];
    const float* ln_b   = (const float*)d_in[14];
    const float* Wo     = (const float*)d_in[15];  // [1024,1024]
    float* out = (float*)d_out;

    float* ax = sym(g_ax); float* xp = sym(g_xp);
    float* am = sym(g_amix);
    float* rb = sym(g_r);  float* kb = sym(g_k);
    float* vb = sym(g_v);  float* gb = sym(g_g);
    float* wd = sym(g_wd); float* ewb = sym(g_ew);
    float* ob = sym(g_o);  float* ogb = sym(g_og);
    float* pb = sym(g_prep); float* sb = sym(g_scal);

    dim3 blk128(128);
    dim3 blk256(256);

    // 1. token-shift lerp with mu_x
    ax_kernel<<<(MT * HH + 255) / 256, blk256>>>(x, mu_x, ax);

    // 2. xp = tanh(ax @ Wx1^T)   [4096,160]
    tgemm_kernel<<<dim3(2, 32, 1), blk256>>>(mk1(ax, Wx1, xp, nullptr),
                                             HH, HH, 160, MT, 160, HH,
                                             1, 0, nullptr);

    // 3. fused 5 mixing GEMMs: a_z = x + (xprev-x)*(xp_z@Wx2_z^T + b_z)
    {
        GemmZ5 d{};
        for (int i = 0; i < 5; i++)
            d.z[i] = GemmZ{xp + i * PRR, Wx2 + i * PRR,
                           am + (long)i * MT * HH, x_bias + i * HH};
        tgemm_kernel<<<dim3(8, 32, 5), blk256>>>(d, 160, 160, HH,
                                                 MT, HH, PRR, 0, 1, x);
    }

    // 4a. fused r + k projections
    {
        GemmZ5 d{};
        d.z[0] = GemmZ{am + 0L * MT * HH, Wr, rb, nullptr};
        d.z[1] = GemmZ{am + 2L * MT * HH, Wk, kb, nullptr};
        tgemm_kernel<<<dim3(4, 32, 2), blk256>>>(d, HH, HH, KD,
                                                 MT, KD, HH, 0, 0, nullptr);
    }
    // 4b. fused v + g projections
    {
        GemmZ5 d{};
        d.z[0] = GemmZ{am + 3L * MT * HH, Wv, vb, nullptr};
        d.z[1] = GemmZ{am + 4L * MT * HH, Wg, gb, nullptr};
        tgemm_kernel<<<dim3(8, 32, 2), blk256>>>(d, HH, HH, VD,
                                                 MT, VD, HH, 0, 0, nullptr);
    }
    // 4c. w LoRA: wd = tanh(a1 @ Ww1^T); ew = exp(-exp(wd @ Ww2^T + bw2))
    tgemm_kernel<<<dim3(1, 32, 1), blk256>>>(mk1(am + 1L * MT * HH, Ww1, wd, nullptr),
                                             HH, HH, GRR, MT, GRR, HH,
                                             1, 0, nullptr);
    tgemm_kernel<<<dim3(4, 32, 1), blk256>>>(mk1(wd, Ww2, ewb, bw2),
                                             GRR, GRR, KD, MT, KD, GRR,
                                             0, 2, nullptr);

    // 5. quad-fusion prep (absorbs bonus-scalar kernel)
    prep4_kernel<<<BB * NQUAD * NHH, blk128>>>(rb, kb, ewb, bonus, pb, sb);

    // 6. 4-token recurrence (128 CTAs, 512 sequential iterations)
    recur4_kernel<<<128, blk256>>>(pb, sb, vb, ob);

    // 7. LayerNorm + swish gate
    ln_kernel<<<MT * NHH, blk256>>>(ob, gb, ln_w, ln_b, ogb);

    // 8. output projection
    tgemm_kernel<<<dim3(8, 32, 1), blk256>>>(mk1(ogb, Wo, out, nullptr),
                                             VD, VD, HH, MT, HH, VD,
                                             0, 0, nullptr);
}

// round 16
// speedup vs baseline: 1.8750x; 1.1337x over previous
#include <cuda_runtime.h>
#include <cstdint>

// Problem constants
#define BB   2
#define LL   2048
#define HH   1024
#define NHH  4
#define KD   512
#define VD   1024
#define DKK  128
#define DVV  256
#define PRR  32
#define GRR  64
#define MT   4096   // total tokens B*L
#define NQUAD 512   // LL/4 token quads per batch

// ---------------- scratch (static __device__, no allocation) ----------------
__device__ float g_ax[MT * HH];
__device__ float g_xp[MT * 160];
__device__ float g_amix[5][MT * HH];
__device__ float g_r [MT * KD];
__device__ float g_k [MT * KD];
__device__ float g_v [MT * VD];
__device__ float g_g [MT * VD];
__device__ float g_wd[MT * GRR];
__device__ float g_ew[MT * KD];
__device__ float g_o [MT * VD];
__device__ float g_og[MT * VD];
__device__ float g_prep[BB * NQUAD * NHH * 1152];
__device__ float g_scal[BB * NQUAD * NHH * 12];
// tf32-converted weights
__device__ float g_cWx1[160 * HH];
__device__ float g_cWx2[HH * 160];
__device__ float g_cWr [KD * HH];
__device__ float g_cWk [KD * HH];
__device__ float g_cWv [VD * HH];
__device__ float g_cWg [VD * HH];
__device__ float g_cWw1[GRR * HH];
__device__ float g_cWw2[KD * GRR];
__device__ float g_cWo [HH * VD];

__device__ __forceinline__ uint32_t f2tf32(float v) {
    uint32_t t;
    asm("cvt.rna.tf32.f32 %0, %1;" : "=r"(t) : "f"(v));
    return t;
}
__device__ __forceinline__ float tf32r(float v) {
    return __uint_as_float(f2tf32(v));
}

// ---------------- weight conversion (fp32 -> tf32-rounded fp32) ------------
struct WC  { const float* src; float* dst; int n; };
struct WC9 { WC w[9]; };
__global__ void wconv_kernel(WC9 d) {
    WC c = d.w[blockIdx.y];
    for (int i = blockIdx.x * blockDim.x + threadIdx.x; i < c.n;
         i += gridDim.x * blockDim.x)
        c.dst[i] = tf32r(c.src[i]);
}

// ---------------- elementwise: ax = tf32(x + (xprev - x)*mu_x) -------------
__global__ void ax_kernel(const float* __restrict__ x,
                          const float* __restrict__ mu_x,
                          float* __restrict__ ax) {
    size_t i = (size_t)blockIdx.x * blockDim.x + threadIdx.x;
    if (i >= (size_t)MT * HH) return;
    int n = (int)(i & (HH - 1));
    size_t m = i >> 10;
    float mu = mu_x[n];
    float xv = x[i];
    float xp = ((m & (LL - 1)) == 0) ? 0.f : x[i - HH];
    ax[i] = tf32r(xv + (xp - xv) * mu);
}

// ---------------- cp.async helpers -----------------------------------------
__device__ __forceinline__ void cpa16(uint32_t dst, const float* src) {
    asm volatile("cp.async.cg.shared.global [%0], [%1], 16;\n"
                 :: "r"(dst), "l"(src));
}
__device__ __forceinline__ void cpa16z(uint32_t dst, const float* src, bool ok) {
    int sz = ok ? 16 : 0;
    asm volatile("cp.async.cg.shared.global [%0], [%1], 16, %2;\n"
                 :: "r"(dst), "l"(src), "r"(sz));
}
__device__ __forceinline__ void cpa_commit() {
    asm volatile("cp.async.commit_group;\n");
}
template <int N>
__device__ __forceinline__ void cpa_wait() {
    asm volatile("cp.async.wait_group %0;\n" :: "n"(N));
}

// ---------------- tf32 tensor-core GEMM, cp.async 3-stage ------------------
// Inputs (A and W) must already be tf32-rounded fp32.
// CTA tile 128x128, BK=16, 8 warps of 64x32. One barrier per k-tile.
struct GemmZ  { const float* A; const float* W; float* C; const float* bias; };
struct GemmZ5 { GemmZ z[5]; };

#define TG_SMEM (3 * 2 * 128 * 20 * 4)   // 61440 bytes

__global__ __launch_bounds__(256, 2)
void tgemm_kernel(GemmZ5 dz, int lda, int ldw, int ldc,
                  int M, int N, int Kdim,
                  int act, int epi, int cvtout,
                  const float* __restrict__ xsrc) {
    const GemmZ gd = dz.z[blockIdx.z];
    const float* A = gd.A;
    const float* W = gd.W;
    float* C = gd.C;
    const float* bias = gd.bias;

    extern __shared__ float sm[];
    float* As = sm;                 // [3][128][20]
    float* Bs = sm + 3 * 2560;      // [3][128][20]

    int tid = threadIdx.x;
    int mBase = blockIdx.y * 128;
    int nBase = blockIdx.x * 128;
    int lr = tid >> 1;
    int lc = (tid & 1) * 8;
    int w = tid >> 5, lane = tid & 31;
    int wm = (w >> 2) * 64;
    int wn = (w & 3) * 32;
    int grp = lane >> 2, tig = lane & 3;

    float acc[4][4][4];
#pragma unroll
    for (int mi = 0; mi < 4; mi++)
#pragma unroll
        for (int ni = 0; ni < 4; ni++)
#pragma unroll
            for (int q = 0; q < 4; q++) acc[mi][ni][q] = 0.f;

    int nt = Kdim >> 4;
    int nrow = nBase + lr;
    bool bok = nrow < N;
    const float* apBase = A + (size_t)(mBase + lr) * lda + lc;
    const float* wpBase = W + (size_t)(bok ? nrow : 0) * ldw + lc;

    uint32_t saBase = (uint32_t)__cvta_generic_to_shared(As) + (lr * 20 + lc) * 4;
    uint32_t sbBase = (uint32_t)__cvta_generic_to_shared(Bs) + (lr * 20 + lc) * 4;

    // prologue: stage tiles 0 and 1 (all K >= 32 so nt >= 2)
#pragma unroll
    for (int s = 0; s < 2; s++) {
        const float* ap = apBase + s * 16;
        const float* wp = wpBase + s * 16;
        uint32_t da = saBase + s * 2560 * 4;
        uint32_t db = sbBase + s * 2560 * 4;
        cpa16(da, ap);       cpa16(da + 16, ap + 4);
        cpa16z(db, wp, bok); cpa16z(db + 16, wp + 4, bok);
        cpa_commit();
    }

    for (int kt = 0; kt < nt; kt++) {
        int cur = kt % 3;
        if (kt + 1 < nt) cpa_wait<1>(); else cpa_wait<0>();
        __syncthreads();
        if (kt + 2 < nt) {
            int s = (kt + 2) % 3;
            const float* ap = apBase + (kt + 2) * 16;
            const float* wp = wpBase + (kt + 2) * 16;
            uint32_t da = saBase + s * 2560 * 4;
            uint32_t db = sbBase + s * 2560 * 4;
            cpa16(da, ap);       cpa16(da + 16, ap + 4);
            cpa16z(db, wp, bok); cpa16z(db + 16, wp + 4, bok);
            cpa_commit();
        }
        const float* Ac = As + cur * 2560;
        const float* Bc = Bs + cur * 2560;
#pragma unroll
        for (int k0 = 0; k0 < 16; k0 += 8) {
            uint32_t af[4][4], bf[4][2];
#pragma unroll
            for (int mi = 0; mi < 4; mi++) {
                int r0 = wm + mi * 16 + grp;
                af[mi][0] = __float_as_uint(Ac[r0 * 20 + k0 + tig]);
                af[mi][1] = __float_as_uint(Ac[(r0 + 8) * 20 + k0 + tig]);
                af[mi][2] = __float_as_uint(Ac[r0 * 20 + k0 + tig + 4]);
                af[mi][3] = __float_as_uint(Ac[(r0 + 8) * 20 + k0 + tig + 4]);
            }
#pragma unroll
            for (int ni = 0; ni < 4; ni++) {
                int c0 = wn + ni * 8 + grp;
                bf[ni][0] = __float_as_uint(Bc[c0 * 20 + k0 + tig]);
                bf[ni][1] = __float_as_uint(Bc[c0 * 20 + k0 + tig + 4]);
            }
#pragma unroll
            for (int mi = 0; mi < 4; mi++)
#pragma unroll
                for (int ni = 0; ni < 4; ni++) {
                    asm volatile(
                        "mma.sync.aligned.m16n8k8.row.col.f32.tf32.tf32.f32 "
                        "{%0,%1,%2,%3}, {%4,%5,%6,%7}, {%8,%9}, {%0,%1,%2,%3};"
                        : "+f"(acc[mi][ni][0]), "+f"(acc[mi][ni][1]),
                          "+f"(acc[mi][ni][2]), "+f"(acc[mi][ni][3])
                        : "r"(af[mi][0]), "r"(af[mi][1]),
                          "r"(af[mi][2]), "r"(af[mi][3]),
                          "r"(bf[ni][0]), "r"(bf[ni][1]));
                }
        }
    }

    // epilogue: float2-vectorized; optionally tf32-round outputs for next GEMM
#pragma unroll
    for (int mi = 0; mi < 4; mi++) {
#pragma unroll
        for (int ni = 0; ni < 4; ni++) {
            int m0 = mBase + wm + mi * 16 + grp;
            int n0 = nBase + wn + ni * 8 + tig * 2;
            if (n0 >= N) continue;
#pragma unroll
            for (int hr = 0; hr < 2; hr++) {
                int m = m0 + hr * 8;
                float vx = acc[mi][ni][hr * 2 + 0];
                float vy = acc[mi][ni][hr * 2 + 1];
                if (bias) { vx += bias[n0]; vy += bias[n0 + 1]; }
                if (act)  { vx = tanhf(vx); vy = tanhf(vy); }
                if (epi == 1) {
                    float2 xv = *(const float2*)&xsrc[(size_t)m * HH + n0];
                    float2 xp = ((m & (LL - 1)) == 0) ? make_float2(0.f, 0.f)
                              : *(const float2*)&xsrc[(size_t)(m - 1) * HH + n0];
                    vx = xv.x + (xp.x - xv.x) * vx;
                    vy = xv.y + (xp.y - xv.y) * vy;
                } else if (epi == 2) {
                    vx = expf(-expf(vx));
                    vy = expf(-expf(vy));
                }
                if (cvtout) { vx = tf32r(vx); vy = tf32r(vy); }
                *(float2*)&C[(size_t)m * ldc + n0] = make_float2(vx, vy);
            }
        }
    }
}

// ---------------- quad-fusion prep ------------------------------------------
__global__ __launch_bounds__(128)
void prep4_kernel(const float* __restrict__ r,
                  const float* __restrict__ k,
                  const float* __restrict__ ew,
                  const float* __restrict__ bonus,
                  float* __restrict__ prep,
                  float* __restrict__ scal) {
    int blk = blockIdx.x;            // ((b*NQUAD+u)*NHH + h)
    int h = blk & 3;
    int bu = blk >> 2;
    int b = bu >> 9, u = bu & (NQUAD - 1);
    int t0 = b * LL + 4 * u;
    int kk = threadIdx.x;
    size_t i0 = (size_t)t0 * KD + h * DKK + kk;
    float r0 = r[i0],          k0 = k[i0],          e0 = ew[i0];
    float r1 = r[i0 + KD],     k1 = k[i0 + KD],     e1 = ew[i0 + KD];
    float r2 = r[i0 + 2 * KD], k2 = k[i0 + 2 * KD], e2 = ew[i0 + 2 * KD];
    float r3 = r[i0 + 3 * KD], k3 = k[i0 + 3 * KD], e3 = ew[i0 + 3 * KD];
    float bo = bonus[h * DKK + kk];

    float p10 = e1 * e0;
    float p210 = e2 * p10;
    float Wp = e3 * p210;
    float s32 = e3 * e2;
    float s321 = s32 * e1;

    float* pp = prep + (size_t)blk * 1152;
    pp[kk]          = r0;
    pp[128 + kk]    = r1 * e0;
    pp[256 + kk]    = r2 * p10;
    pp[384 + kk]    = r3 * p210;
    pp[512 + kk]    = Wp;
    pp[640 + kk]    = k0 * s321;
    pp[768 + kk]    = k1 * s32;
    pp[896 + kk]    = k2 * e3;
    pp[1024 + kk]   = k3;

    float vals[10];
    vals[0] = r0 * bo * k0;
    vals[1] = r1 * bo * k1;
    vals[2] = r2 * bo * k2;
    vals[3] = r3 * bo * k3;
    vals[4] = r1 * k0;               // d10
    vals[5] = r2 * e1 * k0;          // d20
    vals[6] = r2 * k1;               // d21
    vals[7] = r3 * e2 * e1 * k0;     // d30
    vals[8] = r3 * e2 * k1;          // d31
    vals[9] = r3 * k2;               // d32

#pragma unroll
    for (int i = 0; i < 10; i++) {
        float s = vals[i];
#pragma unroll
        for (int off = 16; off; off >>= 1) s += __shfl_xor_sync(0xffffffffu, s, off);
        vals[i] = s;
    }
    __shared__ float sc[10][4];
    int warp = kk >> 5, lane = kk & 31;
    if (!lane) {
#pragma unroll
        for (int i = 0; i < 10; i++) sc[i][warp] = vals[i];
    }
    __syncthreads();
    if (kk < 10) {
        scal[(size_t)blk * 12 + kk] =
            sc[kk][0] + sc[kk][1] + sc[kk][2] + sc[kk][3];
    }
}

// ---------------- 4-token sequential recurrence (128 CTAs) -----------------
#define QV 1152
#define QS 1216
__global__ __launch_bounds__(256)
void recur4_kernel(const float* __restrict__ prep,
                   const float* __restrict__ scal,
                   const float* __restrict__ v,
                   float* __restrict__ o) {
    int blk = blockIdx.x;
    int chain = blk >> 4;
    int vb = blk & 15;
    int b = chain >> 2, h = chain & 3;
    int tid = threadIdx.x;
    int kg = tid >> 4;
    int vi = tid & 15;

    __shared__ float buf[2][1228];
    __shared__ float part[4][272];

    float S[8];
#pragma unroll
    for (int j = 0; j < 8; j++) S[j] = 0.f;

    size_t tb = (size_t)b * LL;
    size_t qBase = ((size_t)b * NQUAD) * 4 + h;

    float pf0 = 0.f, pf1 = 0.f, pf2 = 0.f, pf3 = 0.f, pf4 = 0.f, pv = 0.f, ps = 0.f;

    {
        size_t pb = qBase * 1152;
        pf0 = prep[pb + tid];
        pf1 = prep[pb + 256 + tid];
        pf2 = prep[pb + 512 + tid];
        pf3 = prep[pb + 768 + tid];
        if (tid < 128) pf4 = prep[pb + 1024 + tid];
        if (tid >= 128 && tid < 192) {
            int j = tid - 128;
            pv = v[(tb + (j >> 4)) * VD + h * DVV + vb * 16 + (j & 15)];
        }
        if (tid >= 192 && tid < 202) ps = scal[qBase * 12 + (tid - 192)];
        float* Bn = buf[0];
        Bn[tid] = pf0; Bn[256 + tid] = pf1; Bn[512 + tid] = pf2; Bn[768 + tid] = pf3;
        if (tid < 128) Bn[1024 + tid] = pf4;
        if (tid >= 128 && tid < 192) Bn[QV + tid - 128] = pv;
        if (tid >= 192 && tid < 202) Bn[QS + tid - 192] = ps;
    }
    __syncthreads();

    int pcur = 0;
    for (int u = 0; u < NQUAD; u++) {
        if (u + 1 < NQUAD) {
            size_t pb = (qBase + 4 * (u + 1)) * 1152;
            pf0 = prep[pb + tid];
            pf1 = prep[pb + 256 + tid];
            pf2 = prep[pb + 512 + tid];
            pf3 = prep[pb + 768 + tid];
            if (tid < 128) pf4 = prep[pb + 1024 + tid];
            if (tid >= 128 && tid < 192) {
                int j = tid - 128;
                pv = v[(tb + 4 * (u + 1) + (j >> 4)) * VD + h * DVV + vb * 16 + (j & 15)];
            }
            if (tid >= 192 && tid < 202)
                ps = scal[(qBase + 4 * (u + 1)) * 12 + (tid - 192)];
        }

        const float* Bc = buf[pcur];
        float p0 = 0.f, p1 = 0.f, p2 = 0.f, p3 = 0.f;
#pragma unroll
        for (int j = 0; j < 8; j++) {
            int idx = kg * 8 + j;
            float sj = S[j];
            p0 += Bc[idx] * sj;
            p1 += Bc[128 + idx] * sj;
            p2 += Bc[256 + idx] * sj;
            p3 += Bc[384 + idx] * sj;
        }
        int pidx = kg * 17 + vi;
        part[0][pidx] = p0; part[1][pidx] = p1;
        part[2][pidx] = p2; part[3][pidx] = p3;
        __syncthreads();

        if (tid < 64) {
            int tv = tid >> 4, col = tid & 15;
            float s = 0.f;
#pragma unroll
            for (int g = 0; g < 16; g++) s += part[tv][g * 17 + col];
            float v0 = Bc[QV + col], v1 = Bc[QV + 16 + col];
            float v2 = Bc[QV + 32 + col], v3 = Bc[QV + 48 + col];
            float ov;
            if (tv == 0) {
                ov = s + Bc[QS + 0] * v0;
            } else if (tv == 1) {
                ov = s + Bc[QS + 4] * v0 + Bc[QS + 1] * v1;
            } else if (tv == 2) {
                ov = s + Bc[QS + 5] * v0 + Bc[QS + 6] * v1 + Bc[QS + 2] * v2;
            } else {
                ov = s + Bc[QS + 7] * v0 + Bc[QS + 8] * v1
                       + Bc[QS + 9] * v2 + Bc[QS + 3] * v3;
            }
            o[(tb + 4 * u + tv) * VD + h * DVV + vb * 16 + col] = ov;
        }

        float v0 = Bc[QV + vi], v1 = Bc[QV + 16 + vi];
        float v2 = Bc[QV + 32 + vi], v3 = Bc[QV + 48 + vi];
#pragma unroll
        for (int j = 0; j < 8; j++) {
            int idx = kg * 8 + j;
            S[j] = Bc[512 + idx] * S[j] + Bc[640 + idx] * v0 + Bc[768 + idx] * v1
                 + Bc[896 + idx] * v2 + Bc[1024 + idx] * v3;
        }

        if (u + 1 < NQUAD) {
            float* Bn = buf[pcur ^ 1];
            Bn[tid] = pf0; Bn[256 + tid] = pf1; Bn[512 + tid] = pf2; Bn[768 + tid] = pf3;
            if (tid < 128) Bn[1024 + tid] = pf4;
            if (tid >= 128 && tid < 192) Bn[QV + tid - 128] = pv;
            if (tid >= 192 && tid < 202) Bn[QS + tid - 192] = ps;
        }
        __syncthreads();
        pcur ^= 1;
    }
}

// ---------------- per-head LayerNorm + swish gate (tf32 out for Wo) -------
__global__ __launch_bounds__(256)
void ln_kernel(const float* __restrict__ o,
               const float* __restrict__ g,
               const float* __restrict__ ln_w,
               const float* __restrict__ ln_b,
               float* __restrict__ og) {
    int th = blockIdx.x;
    int t = th >> 2, h = th & 3;
    int vv = threadIdx.x;
    size_t idx = (size_t)t * VD + h * DVV + vv;
    float val = o[idx];

    __shared__ float rs[8], rs2[8];
    float s1 = val, s2 = val * val;
#pragma unroll
    for (int off = 16; off; off >>= 1) {
        s1 += __shfl_xor_sync(0xffffffffu, s1, off);
        s2 += __shfl_xor_sync(0xffffffffu, s2, off);
    }
    int warp = vv >> 5, lane = vv & 31;
    if (!lane) { rs[warp] = s1; rs2[warp] = s2; }
    __syncthreads();
    float tot = 0.f, tot2 = 0.f;
#pragma unroll
    for (int i = 0; i < 8; i++) { tot += rs[i]; tot2 += rs2[i]; }
    float mean = tot * (1.f / DVV);
    float var = tot2 * (1.f / DVV) - mean * mean;
    float inv = rsqrtf(var + 1e-5f);
    float on = (val - mean) * inv * ln_w[vv] + ln_b[vv];
    float gv = g[idx];
    og[idx] = tf32r(on * gv * (1.f / (1.f + expf(-gv))));
}

// ---------------- host launcher -----------------------------------------
static float* sym(const void* s) {
    void* p = nullptr;
    cudaGetSymbolAddress(&p, s);
    return (float*)p;
}

static GemmZ5 mk1(const float* A, const float* W, float* C, const float* bias) {
    GemmZ5 d{};
    d.z[0] = GemmZ{A, W, C, bias};
    return d;
}

extern "C" void kernel_launch(void* const* d_in, const int* in_sizes, int n_in,
                              void* d_out, int out_size) {
    const float* x      = (const float*)d_in[0];
    const float* mu_x   = (const float*)d_in[1];
    const float* Wx1    = (const float*)d_in[2];   // [160,1024]
    const float* Wx2    = (const float*)d_in[3];   // [1024,160]
    const float* x_bias = (const float*)d_in[4];   // [5,1024]
    const float* Wr     = (const float*)d_in[5];   // [512,1024]
    const float* Wk     = (const float*)d_in[6];
    const float* Wv     = (const float*)d_in[7];   // [1024,1024]
    const float* Wg     = (const float*)d_in[8];
    const float* Ww1    = (const float*)d_in[9];   // [64,1024]
    const float* Ww2    = (const float*)d_in[10];  // [512,64]
    const float* bw2    = (const float*)d_in[11];  // [512]
    const float* bonus  = (const float*)d_in[12];  // [4,128]
    const float* ln_w   = (const float*)d_in[13];
    const float* ln_b   = (const float*)d_in[14];
    const float* Wo     = (const float*)d_in[15];  // [1024,1024]
    float* out = (float*)d_out;

    float* ax = sym(g_ax); float* xp = sym(g_xp);
    float* am = sym(g_amix);
    float* rb = sym(g_r);  float* kb = sym(g_k);
    float* vb = sym(g_v);  float* gb = sym(g_g);
    float* wd = sym(g_wd); float* ewb = sym(g_ew);
    float* ob = sym(g_o);  float* ogb = sym(g_og);
    float* pb = sym(g_prep); float* sb = sym(g_scal);
    float* cWx1 = sym(g_cWx1); float* cWx2 = sym(g_cWx2);
    float* cWr = sym(g_cWr);   float* cWk = sym(g_cWk);
    float* cWv = sym(g_cWv);   float* cWg = sym(g_cWg);
    float* cWw1 = sym(g_cWw1); float* cWw2 = sym(g_cWw2);
    float* cWo = sym(g_cWo);

    dim3 blk128(128);
    dim3 blk256(256);

    cudaFuncSetAttribute(tgemm_kernel,
                         cudaFuncAttributeMaxDynamicSharedMemorySize, TG_SMEM);

    // 0. weight conversion to tf32
    {
        WC9 d{};
        d.w[0] = WC{Wx1, cWx1, 160 * HH};
        d.w[1] = WC{Wx2, cWx2, HH * 160};
        d.w[2] = WC{Wr,  cWr,  KD * HH};
        d.w[3] = WC{Wk,  cWk,  KD * HH};
        d.w[4] = WC{Wv,  cWv,  VD * HH};
        d.w[5] = WC{Wg,  cWg,  VD * HH};
        d.w[6] = WC{Ww1, cWw1, GRR * HH};
        d.w[7] = WC{Ww2, cWw2, KD * GRR};
        d.w[8] = WC{Wo,  cWo,  HH * VD};
        wconv_kernel<<<dim3(512, 9), blk256>>>(d);
    }

    // 1. token-shift lerp with mu_x (tf32 out)
    ax_kernel<<<(MT * HH + 255) / 256, blk256>>>(x, mu_x, ax);

    // 2. xp = tanh(ax @ Wx1^T) (tf32 out)
    tgemm_kernel<<<dim3(2, 32, 1), blk256, TG_SMEM>>>(
        mk1(ax, cWx1, xp, nullptr), HH, HH, 160, MT, 160, HH, 1, 0, 1, nullptr);

    // 3. fused 5 mixing GEMMs (tf32 out)
    {
        GemmZ5 d{};
        for (int i = 0; i < 5; i++)
            d.z[i] = GemmZ{xp + i * PRR, cWx2 + i * PRR,
                           am + (long)i * MT * HH, x_bias + i * HH};
        tgemm_kernel<<<dim3(8, 32, 5), blk256, TG_SMEM>>>(
            d, 160, 160, HH, MT, HH, PRR, 0, 1, 1, x);
    }

    // 4a. fused r + k projections (fp32 out)
    {
        GemmZ5 d{};
        d.z[0] = GemmZ{am + 0L * MT * HH, cWr, rb, nullptr};
        d.z[1] = GemmZ{am + 2L * MT * HH, cWk, kb, nullptr};
        tgemm_kernel<<<dim3(4, 32, 2), blk256, TG_SMEM>>>(
            d, HH, HH, KD, MT, KD, HH, 0, 0, 0, nullptr);
    }
    // 4b. fused v + g projections (fp32 out)
    {
        GemmZ5 d{};
        d.z[0] = GemmZ{am + 3L * MT * HH, cWv, vb, nullptr};
        d.z[1] = GemmZ{am + 4L * MT * HH, cWg, gb, nullptr};
        tgemm_kernel<<<dim3(8, 32, 2), blk256, TG_SMEM>>>(
            d, HH, HH, VD, MT, VD, HH, 0, 0, 0, nullptr);
    }
    // 4c. w LoRA
    tgemm_kernel<<<dim3(1, 32, 1), blk256, TG_SMEM>>>(
        mk1(am + 1L * MT * HH, cWw1, wd, nullptr),
        HH, HH, GRR, MT, GRR, HH, 1, 0, 1, nullptr);
    tgemm_kernel<<<dim3(4, 32, 1), blk256, TG_SMEM>>>(
        mk1(wd, cWw2, ewb, bw2),
        GRR, GRR, KD, MT, KD, GRR, 0, 2, 0, nullptr);

    // 5. quad-fusion prep
    prep4_kernel<<<BB * NQUAD * NHH, blk128>>>(rb, kb, ewb, bonus, pb, sb);

    // 6. 4-token recurrence
    recur4_kernel<<<128, blk256>>>(pb, sb, vb, ob);

    // 7. LayerNorm + swish gate (tf32 out)
    ln_kernel<<<MT * NHH, blk256>>>(ob, gb, ln_w, ln_b, ogb);

    // 8. output projection (fp32 out)
    tgemm_kernel<<<dim3(8, 32, 1), blk256, TG_SMEM>>>(
        mk1(ogb, cWo, out, nullptr),
        VD, VD, HH, MT, HH, VD, 0, 0, 0, nullptr);
}

// round 17
// speedup vs baseline: 2.3357x; 1.2457x over previous
#include <cuda_runtime.h>
#include <cstdint>

// Problem constants
#define BB   2
#define LL   2048
#define HH   1024
#define NHH  4
#define KD   512
#define VD   1024
#define DKK  128
#define DVV  256
#define PRR  32
#define GRR  64
#define MT   4096   // total tokens B*L
#define NQ8  256    // LL/8 token octets per batch

// ---------------- scratch (static __device__, no allocation) ----------------
__device__ float g_ax[MT * HH];
__device__ float g_xp[MT * 160];
__device__ float g_amix[5][MT * HH];
__device__ float g_r [MT * KD];
__device__ float g_k [MT * KD];
__device__ float g_v [MT * VD];
__device__ float g_g [MT * VD];
__device__ float g_wd[MT * GRR];
__device__ float g_ew[MT * KD];
__device__ float g_o [MT * VD];
__device__ float g_og[MT * VD];
__device__ __align__(16) float g_prep[BB * NQ8 * NHH * 2176];  // 17 vec per octet
__device__ float g_scal[BB * NQ8 * NHH * 36];                  // c0..c7 + 28 d
// tf32-converted weights
__device__ float g_cWx1[160 * HH];
__device__ float g_cWx2[HH * 160];
__device__ float g_cWr [KD * HH];
__device__ float g_cWk [KD * HH];
__device__ float g_cWv [VD * HH];
__device__ float g_cWg [VD * HH];
__device__ float g_cWw1[GRR * HH];
__device__ float g_cWw2[KD * GRR];
__device__ float g_cWo [HH * VD];

__device__ __forceinline__ uint32_t f2tf32(float v) {
    uint32_t t;
    asm("cvt.rna.tf32.f32 %0, %1;" : "=r"(t) : "f"(v));
    return t;
}
__device__ __forceinline__ float tf32r(float v) {
    return __uint_as_float(f2tf32(v));
}

// ---------------- weight conversion (fp32 -> tf32-rounded fp32) ------------
struct WC  { const float* src; float* dst; int n; };
struct WC9 { WC w[9]; };
__global__ void wconv_kernel(WC9 d) {
    WC c = d.w[blockIdx.y];
    for (int i = blockIdx.x * blockDim.x + threadIdx.x; i < c.n;
         i += gridDim.x * blockDim.x)
        c.dst[i] = tf32r(c.src[i]);
}

// ---------------- elementwise: ax = tf32(x + (xprev - x)*mu_x) -------------
__global__ void ax_kernel(const float* __restrict__ x,
                          const float* __restrict__ mu_x,
                          float* __restrict__ ax) {
    size_t i = (size_t)blockIdx.x * blockDim.x + threadIdx.x;
    if (i >= (size_t)MT * HH) return;
    int n = (int)(i & (HH - 1));
    size_t m = i >> 10;
    float mu = mu_x[n];
    float xv = x[i];
    float xp = ((m & (LL - 1)) == 0) ? 0.f : x[i - HH];
    ax[i] = tf32r(xv + (xp - xv) * mu);
}

// ---------------- cp.async helpers -----------------------------------------
__device__ __forceinline__ void cpa16(uint32_t dst, const float* src) {
    asm volatile("cp.async.cg.shared.global [%0], [%1], 16;\n"
                 :: "r"(dst), "l"(src));
}
__device__ __forceinline__ void cpa16z(uint32_t dst, const float* src, bool ok) {
    int sz = ok ? 16 : 0;
    asm volatile("cp.async.cg.shared.global [%0], [%1], 16, %2;\n"
                 :: "r"(dst), "l"(src), "r"(sz));
}
__device__ __forceinline__ void cpa_commit() {
    asm volatile("cp.async.commit_group;\n");
}
template <int N>
__device__ __forceinline__ void cpa_wait() {
    asm volatile("cp.async.wait_group %0;\n" :: "n"(N));
}

// ---------------- tf32 tensor-core GEMM, cp.async 3-stage ------------------
struct GemmZ  { const float* A; const float* W; float* C; const float* bias; };
struct GemmZ5 { GemmZ z[5]; };

#define TG_SMEM (3 * 2 * 128 * 20 * 4)   // 61440 bytes

__global__ __launch_bounds__(256, 2)
void tgemm_kernel(GemmZ5 dz, int lda, int ldw, int ldc,
                  int M, int N, int Kdim,
                  int act, int epi, int cvtout,
                  const float* __restrict__ xsrc) {
    const GemmZ gd = dz.z[blockIdx.z];
    const float* A = gd.A;
    const float* W = gd.W;
    float* C = gd.C;
    const float* bias = gd.bias;

    extern __shared__ float sm[];
    float* As = sm;                 // [3][128][20]
    float* Bs = sm + 3 * 2560;      // [3][128][20]

    int tid = threadIdx.x;
    int mBase = blockIdx.y * 128;
    int nBase = blockIdx.x * 128;
    int lr = tid >> 1;
    int lc = (tid & 1) * 8;
    int w = tid >> 5, lane = tid & 31;
    int wm = (w >> 2) * 64;
    int wn = (w & 3) * 32;
    int grp = lane >> 2, tig = lane & 3;

    float acc[4][4][4];
#pragma unroll
    for (int mi = 0; mi < 4; mi++)
#pragma unroll
        for (int ni = 0; ni < 4; ni++)
#pragma unroll
            for (int q = 0; q < 4; q++) acc[mi][ni][q] = 0.f;

    int nt = Kdim >> 4;
    int nrow = nBase + lr;
    bool bok = nrow < N;
    const float* apBase = A + (size_t)(mBase + lr) * lda + lc;
    const float* wpBase = W + (size_t)(bok ? nrow : 0) * ldw + lc;

    uint32_t saBase = (uint32_t)__cvta_generic_to_shared(As) + (lr * 20 + lc) * 4;
    uint32_t sbBase = (uint32_t)__cvta_generic_to_shared(Bs) + (lr * 20 + lc) * 4;

#pragma unroll
    for (int s = 0; s < 2; s++) {
        const float* ap = apBase + s * 16;
        const float* wp = wpBase + s * 16;
        uint32_t da = saBase + s * 2560 * 4;
        uint32_t db = sbBase + s * 2560 * 4;
        cpa16(da, ap);       cpa16(da + 16, ap + 4);
        cpa16z(db, wp, bok); cpa16z(db + 16, wp + 4, bok);
        cpa_commit();
    }

    for (int kt = 0; kt < nt; kt++) {
        int cur = kt % 3;
        if (kt + 1 < nt) cpa_wait<1>(); else cpa_wait<0>();
        __syncthreads();
        if (kt + 2 < nt) {
            int s = (kt + 2) % 3;
            const float* ap = apBase + (kt + 2) * 16;
            const float* wp = wpBase + (kt + 2) * 16;
            uint32_t da = saBase + s * 2560 * 4;
            uint32_t db = sbBase + s * 2560 * 4;
            cpa16(da, ap);       cpa16(da + 16, ap + 4);
            cpa16z(db, wp, bok); cpa16z(db + 16, wp + 4, bok);
            cpa_commit();
        }
        const float* Ac = As + cur * 2560;
        const float* Bc = Bs + cur * 2560;
#pragma unroll
        for (int k0 = 0; k0 < 16; k0 += 8) {
            uint32_t af[4][4], bf[4][2];
#pragma unroll
            for (int mi = 0; mi < 4; mi++) {
                int r0 = wm + mi * 16 + grp;
                af[mi][0] = __float_as_uint(Ac[r0 * 20 + k0 + tig]);
                af[mi][1] = __float_as_uint(Ac[(r0 + 8) * 20 + k0 + tig]);
                af[mi][2] = __float_as_uint(Ac[r0 * 20 + k0 + tig + 4]);
                af[mi][3] = __float_as_uint(Ac[(r0 + 8) * 20 + k0 + tig + 4]);
            }
#pragma unroll
            for (int ni = 0; ni < 4; ni++) {
                int c0 = wn + ni * 8 + grp;
                bf[ni][0] = __float_as_uint(Bc[c0 * 20 + k0 + tig]);
                bf[ni][1] = __float_as_uint(Bc[c0 * 20 + k0 + tig + 4]);
            }
#pragma unroll
            for (int mi = 0; mi < 4; mi++)
#pragma unroll
                for (int ni = 0; ni < 4; ni++) {
                    asm volatile(
                        "mma.sync.aligned.m16n8k8.row.col.f32.tf32.tf32.f32 "
                        "{%0,%1,%2,%3}, {%4,%5,%6,%7}, {%8,%9}, {%0,%1,%2,%3};"
                        : "+f"(acc[mi][ni][0]), "+f"(acc[mi][ni][1]),
                          "+f"(acc[mi][ni][2]), "+f"(acc[mi][ni][3])
                        : "r"(af[mi][0]), "r"(af[mi][1]),
                          "r"(af[mi][2]), "r"(af[mi][3]),
                          "r"(bf[ni][0]), "r"(bf[ni][1]));
                }
        }
    }

#pragma unroll
    for (int mi = 0; mi < 4; mi++) {
#pragma unroll
        for (int ni = 0; ni < 4; ni++) {
            int m0 = mBase + wm + mi * 16 + grp;
            int n0 = nBase + wn + ni * 8 + tig * 2;
            if (n0 >= N) continue;
#pragma unroll
            for (int hr = 0; hr < 2; hr++) {
                int m = m0 + hr * 8;
                float vx = acc[mi][ni][hr * 2 + 0];
                float vy = acc[mi][ni][hr * 2 + 1];
                if (bias) { vx += bias[n0]; vy += bias[n0 + 1]; }
                if (act)  { vx = tanhf(vx); vy = tanhf(vy); }
                if (epi == 1) {
                    float2 xv = *(const float2*)&xsrc[(size_t)m * HH + n0];
                    float2 xp = ((m & (LL - 1)) == 0) ? make_float2(0.f, 0.f)
                              : *(const float2*)&xsrc[(size_t)(m - 1) * HH + n0];
                    vx = xv.x + (xp.x - xv.x) * vx;
                    vy = xv.y + (xp.y - xv.y) * vy;
                } else if (epi == 2) {
                    vx = expf(-expf(vx));
                    vy = expf(-expf(vy));
                }
                if (cvtout) { vx = tf32r(vx); vy = tf32r(vy); }
                *(float2*)&C[(size_t)m * ldc + n0] = make_float2(vx, vy);
            }
        }
    }
}

// ---------------- octet-fusion prep (T=8) -----------------------------------
// Vectors per octet block (17 x 128): aR_t = r_t*prod_{j<t}e_j (t=0..7),
// W = prod e_j (at 1024), bK_s = k_s*prod_{j>s}e_j (at 1152+s*128).
// Scalars (36): c_t = r_t.bonus.k_t (0..7); d_{t,s} at 8 + t(t-1)/2 + s.
__global__ __launch_bounds__(128)
void prep8_kernel(const float* __restrict__ r,
                  const float* __restrict__ k,
                  const float* __restrict__ ew,
                  const float* __restrict__ bonus,
                  float* __restrict__ prep,
                  float* __restrict__ scal) {
    int blk = blockIdx.x;            // ((b*NQ8+u)*NHH + h)
    int h = blk & 3;
    int bu = blk >> 2;
    int b = bu >> 8, u = bu & (NQ8 - 1);
    int t0 = b * LL + 8 * u;
    int kk = threadIdx.x;
    size_t i0 = (size_t)t0 * KD + h * DKK + kk;

    float rr[8], kv[8], ee[8];
#pragma unroll
    for (int t = 0; t < 8; t++) {
        rr[t] = r [i0 + (size_t)t * KD];
        kv[t] = k [i0 + (size_t)t * KD];
        ee[t] = ew[i0 + (size_t)t * KD];
    }
    float bo = bonus[h * DKK + kk];

    float* pp = prep + (size_t)blk * 2176;
    float P = 1.f;
#pragma unroll
    for (int t = 0; t < 8; t++) { pp[t * 128 + kk] = rr[t] * P; P *= ee[t]; }
    pp[1024 + kk] = P;
    float Q = 1.f;
#pragma unroll
    for (int t = 7; t >= 0; t--) { pp[1152 + t * 128 + kk] = kv[t] * Q; Q *= ee[t]; }

    float vals[36];
#pragma unroll
    for (int t = 0; t < 8; t++) vals[t] = rr[t] * bo * kv[t];
#pragma unroll
    for (int t = 1; t < 8; t++) {
        int base = 8 + t * (t - 1) / 2;
        float E = 1.f;
#pragma unroll
        for (int s = t - 1; s >= 0; s--) {
            vals[base + s] = rr[t] * E * kv[s];
            E *= ee[s];
        }
    }

#pragma unroll
    for (int i = 0; i < 36; i++) {
        float s = vals[i];
#pragma unroll
        for (int off = 16; off; off >>= 1) s += __shfl_xor_sync(0xffffffffu, s, off);
        vals[i] = s;
    }
    __shared__ float sc[36][4];
    int warp = kk >> 5, lane = kk & 31;
    if (!lane) {
#pragma unroll
        for (int i = 0; i < 36; i++) sc[i][warp] = vals[i];
    }
    __syncthreads();
    if (kk < 36)
        scal[(size_t)blk * 36 + kk] = sc[kk][0] + sc[kk][1] + sc[kk][2] + sc[kk][3];
}

// ---------------- 8-token sequential recurrence (128 CTAs) -----------------
// 16 CTAs per chain, 16 v-cols each. kg=tid/16 owns 8 k (float4-pair loads),
// vi=tid%16. 2 barriers per 8 tokens.
#define V8OFF 2176
#define S8OFF 2304
__global__ __launch_bounds__(256)
void recur8_kernel(const float* __restrict__ prep,
                   const float* __restrict__ scal,
                   const float* __restrict__ v,
                   float* __restrict__ o) {
    int blk = blockIdx.x;
    int chain = blk >> 4;
    int vb = blk & 15;
    int b = chain >> 2, h = chain & 3;
    int tid = threadIdx.x;
    int kg = tid >> 4;
    int vi = tid & 15;

    __shared__ __align__(16) float buf[2][2352];
    __shared__ float part[8][272];

    float S[8];
#pragma unroll
    for (int j = 0; j < 8; j++) S[j] = 0.f;

    size_t tb = (size_t)b * LL;
    size_t q8 = (size_t)b * NQ8 * 4 + h;   // block index; +4 per octet

    float4 pa = {0,0,0,0}, pbv = {0,0,0,0}, pc = {0,0,0,0}, pv4 = {0,0,0,0};
    float ps = 0.f;

    // prologue: load octet 0
    {
        const float4* p4 = (const float4*)prep + q8 * 544;
        pa = p4[tid];
        pbv = p4[256 + tid];
        if (tid < 32) pc = p4[512 + tid];
        if (tid >= 32 && tid < 64) {
            int j = tid - 32;
            pv4 = *(const float4*)&v[(tb + (j >> 2)) * VD + h * DVV
                                     + vb * 16 + (j & 3) * 4];
        }
        if (tid >= 64 && tid < 100) ps = scal[q8 * 36 + (tid - 64)];
        float4* B4 = (float4*)buf[0];
        B4[tid] = pa; B4[256 + tid] = pbv;
        if (tid < 32) B4[512 + tid] = pc;
        if (tid >= 32 && tid < 64) B4[544 + (tid - 32)] = pv4;
        if (tid >= 64 && tid < 100) buf[0][S8OFF + tid - 64] = ps;
    }
    __syncthreads();

    int pcur = 0;
    for (int u = 0; u < NQ8; u++) {
        // prefetch octet u+1
        if (u + 1 < NQ8) {
            const float4* p4 = (const float4*)prep + (q8 + 4 * (u + 1)) * 544;
            pa = p4[tid];
            pbv = p4[256 + tid];
            if (tid < 32) pc = p4[512 + tid];
            if (tid >= 32 && tid < 64) {
                int j = tid - 32;
                pv4 = *(const float4*)&v[(tb + 8 * (u + 1) + (j >> 2)) * VD
                                         + h * DVV + vb * 16 + (j & 3) * 4];
            }
            if (tid >= 64 && tid < 100)
                ps = scal[(q8 + 4 * (u + 1)) * 36 + (tid - 64)];
        }

        const float* Bc = buf[pcur];
        // o partials for 8 tokens (float4 operand loads)
#pragma unroll
        for (int t = 0; t < 8; t++) {
            float4 a0 = *(const float4*)&Bc[t * 128 + kg * 8];
            float4 a1 = *(const float4*)&Bc[t * 128 + kg * 8 + 4];
            float p = a0.x * S[0] + a0.y * S[1] + a0.z * S[2] + a0.w * S[3]
                    + a1.x * S[4] + a1.y * S[5] + a1.z * S[6] + a1.w * S[7];
            part[t][kg * 17 + vi] = p;
        }
        __syncthreads();

        if (tid < 128) {
            int tv = tid >> 4, col = tid & 15;
            float s = 0.f;
#pragma unroll
            for (int g = 0; g < 16; g++) s += part[tv][g * 17 + col];
            float ov = s + Bc[S8OFF + tv] * Bc[V8OFF + tv * 16 + col];
            int dbase = S8OFF + 8 + tv * (tv - 1) / 2;
#pragma unroll
            for (int ss = 0; ss < 7; ss++)
                if (ss < tv)
                    ov += Bc[dbase + ss] * Bc[V8OFF + ss * 16 + col];
            o[(tb + 8 * u + tv) * VD + h * DVV + vb * 16 + col] = ov;
        }

        // state update: S = W*S + sum_s bK_s*v_s
        float vv[8];
#pragma unroll
        for (int s = 0; s < 8; s++) vv[s] = Bc[V8OFF + s * 16 + vi];
        {
            float4 w0 = *(const float4*)&Bc[1024 + kg * 8];
            float4 w1 = *(const float4*)&Bc[1024 + kg * 8 + 4];
            S[0] *= w0.x; S[1] *= w0.y; S[2] *= w0.z; S[3] *= w0.w;
            S[4] *= w1.x; S[5] *= w1.y; S[6] *= w1.z; S[7] *= w1.w;
        }
#pragma unroll
        for (int s = 0; s < 8; s++) {
            float4 b0 = *(const float4*)&Bc[1152 + s * 128 + kg * 8];
            float4 b1 = *(const float4*)&Bc[1152 + s * 128 + kg * 8 + 4];
            float vs = vv[s];
            S[0] += b0.x * vs; S[1] += b0.y * vs; S[2] += b0.z * vs; S[3] += b0.w * vs;
            S[4] += b1.x * vs; S[5] += b1.y * vs; S[6] += b1.z * vs; S[7] += b1.w * vs;
        }

        // stage prefetched octet
        if (u + 1 < NQ8) {
            float4* B4 = (float4*)buf[pcur ^ 1];
            B4[tid] = pa; B4[256 + tid] = pbv;
            if (tid < 32) B4[512 + tid] = pc;
            if (tid >= 32 && tid < 64) B4[544 + (tid - 32)] = pv4;
            if (tid >= 64 && tid < 100) buf[pcur ^ 1][S8OFF + tid - 64] = ps;
        }
        __syncthreads();
        pcur ^= 1;
    }
}

// ---------------- per-head LayerNorm + swish gate (tf32 out for Wo) -------
__global__ __launch_bounds__(256)
void ln_kernel(const float* __restrict__ o,
               const float* __restrict__ g,
               const float* __restrict__ ln_w,
               const float* __restrict__ ln_b,
               float* __restrict__ og) {
    int th = blockIdx.x;
    int t = th >> 2, h = th & 3;
    int vv = threadIdx.x;
    size_t idx = (size_t)t * VD + h * DVV + vv;
    float val = o[idx];

    __shared__ float rs[8], rs2[8];
    float s1 = val, s2 = val * val;
#pragma unroll
    for (int off = 16; off; off >>= 1) {
        s1 += __shfl_xor_sync(0xffffffffu, s1, off);
        s2 += __shfl_xor_sync(0xffffffffu, s2, off);
    }
    int warp = vv >> 5, lane = vv & 31;
    if (!lane) { rs[warp] = s1; rs2[warp] = s2; }
    __syncthreads();
    float tot = 0.f, tot2 = 0.f;
#pragma unroll
    for (int i = 0; i < 8; i++) { tot += rs[i]; tot2 += rs2[i]; }
    float mean = tot * (1.f / DVV);
    float var = tot2 * (1.f / DVV) - mean * mean;
    float inv = rsqrtf(var + 1e-5f);
    float on = (val - mean) * inv * ln_w[vv] + ln_b[vv];
    float gv = g[idx];
    og[idx] = tf32r(on * gv * (1.f / (1.f + expf(-gv))));
}

// ---------------- host launcher -----------------------------------------
static float* sym(const void* s) {
    void* p = nullptr;
    cudaGetSymbolAddress(&p, s);
    return (float*)p;
}

static GemmZ5 mk1(const float* A, const float* W, float* C, const float* bias) {
    GemmZ5 d{};
    d.z[0] = GemmZ{A, W, C, bias};
    return d;
}

extern "C" void kernel_launch(void* const* d_in, const int* in_sizes, int n_in,
                              void* d_out, int out_size) {
    const float* x      = (const float*)d_in[0];
    const float* mu_x   = (const float*)d_in[1];
    const float* Wx1    = (const float*)d_in[2];   // [160,1024]
    const float* Wx2    = (const float*)d_in[3];   // [1024,160]
    const float* x_bias = (const float*)d_in[4];   // [5,1024]
    const float* Wr     = (const float*)d_in[5];   // [512,1024]
    const float* Wk     = (const float*)d_in[6];
    const float* Wv     = (const float*)d_in[7];   // [1024,1024]
    const float* Wg     = (const float*)d_in[8];
    const float* Ww1    = (const float*)d_in[9];   // [64,1024]
    const float* Ww2    = (const float*)d_in[10];  // [512,64]
    const float* bw2    = (const float*)d_in[11];  // [512]
    const float* bonus  = (const float*)d_in[12];  // [4,128]
    const float* ln_w   = (const float*)d_in[13];
    const float* ln_b   = (const float*)d_in[14];
    const float* Wo     = (const float*)d_in[15];  // [1024,1024]
    float* out = (float*)d_out;

    float* ax = sym(g_ax); float* xp = sym(g_xp);
    float* am = sym(g_amix);
    float* rb = sym(g_r);  float* kb = sym(g_k);
    float* vb = sym(g_v);  float* gb = sym(g_g);
    float* wd = sym(g_wd); float* ewb = sym(g_ew);
    float* ob = sym(g_o);  float* ogb = sym(g_og);
    float* pb = sym(g_prep); float* sb = sym(g_scal);
    float* cWx1 = sym(g_cWx1); float* cWx2 = sym(g_cWx2);
    float* cWr = sym(g_cWr);   float* cWk = sym(g_cWk);
    float* cWv = sym(g_cWv);   float* cWg = sym(g_cWg);
    float* cWw1 = sym(g_cWw1); float* cWw2 = sym(g_cWw2);
    float* cWo = sym(g_cWo);

    dim3 blk128(128);
    dim3 blk256(256);

    cudaFuncSetAttribute(tgemm_kernel,
                         cudaFuncAttributeMaxDynamicSharedMemorySize, TG_SMEM);

    // 0. weight conversion to tf32
    {
        WC9 d{};
        d.w[0] = WC{Wx1, cWx1, 160 * HH};
        d.w[1] = WC{Wx2, cWx2, HH * 160};
        d.w[2] = WC{Wr,  cWr,  KD * HH};
        d.w[3] = WC{Wk,  cWk,  KD * HH};
        d.w[4] = WC{Wv,  cWv,  VD * HH};
        d.w[5] = WC{Wg,  cWg,  VD * HH};
        d.w[6] = WC{Ww1, cWw1, GRR * HH};
        d.w[7] = WC{Ww2, cWw2, KD * GRR};
        d.w[8] = WC{Wo,  cWo,  HH * VD};
        wconv_kernel<<<dim3(512, 9), blk256>>>(d);
    }

    // 1. token-shift lerp with mu_x (tf32 out)
    ax_kernel<<<(MT * HH + 255) / 256, blk256>>>(x, mu_x, ax);

    // 2. xp = tanh(ax @ Wx1^T) (tf32 out)
    tgemm_kernel<<<dim3(2, 32, 1), blk256, TG_SMEM>>>(
        mk1(ax, cWx1, xp, nullptr), HH, HH, 160, MT, 160, HH, 1, 0, 1, nullptr);

    // 3. fused 5 mixing GEMMs (tf32 out)
    {
        GemmZ5 d{};
        for (int i = 0; i < 5; i++)
            d.z[i] = GemmZ{xp + i * PRR, cWx2 + i * PRR,
                           am + (long)i * MT * HH, x_bias + i * HH};
        tgemm_kernel<<<dim3(8, 32, 5), blk256, TG_SMEM>>>(
            d, 160, 160, HH, MT, HH, PRR, 0, 1, 1, x);
    }

    // 4a. fused r + k projections (fp32 out)
    {
        GemmZ5 d{};
        d.z[0] = GemmZ{am + 0L * MT * HH, cWr, rb, nullptr};
        d.z[1] = GemmZ{am + 2L * MT * HH, cWk, kb, nullptr};
        tgemm_kernel<<<dim3(4, 32, 2), blk256, TG_SMEM>>>(
            d, HH, HH, KD, MT, KD, HH, 0, 0, 0, nullptr);
    }
    // 4b. fused v + g projections (fp32 out)
    {
        GemmZ5 d{};
        d.z[0] = GemmZ{am + 3L * MT * HH, cWv, vb, nullptr};
        d.z[1] = GemmZ{am + 4L * MT * HH, cWg, gb, nullptr};
        tgemm_kernel<<<dim3(8, 32, 2), blk256, TG_SMEM>>>(
            d, HH, HH, VD, MT, VD, HH, 0, 0, 0, nullptr);
    }
    // 4c. w LoRA
    tgemm_kernel<<<dim3(1, 32, 1), blk256, TG_SMEM>>>(
        mk1(am + 1L * MT * HH, cWw1, wd, nullptr),
        HH, HH, GRR, MT, GRR, HH, 1, 0, 1, nullptr);
    tgemm_kernel<<<dim3(4, 32, 1), blk256, TG_SMEM>>>(
        mk1(wd, cWw2, ewb, bw2),
        GRR, GRR, KD, MT, KD, GRR, 0, 2, 0, nullptr);

    // 5. octet-fusion prep
    prep8_kernel<<<BB * NQ8 * NHH, blk128>>>(rb, kb, ewb, bonus, pb, sb);

    // 6. 8-token recurrence (128 CTAs, 256 sequential iterations)
    recur8_kernel<<<128, blk256>>>(pb, sb, vb, ob);

    // 7. LayerNorm + swish gate (tf32 out)
    ln_kernel<<<MT * NHH, blk256>>>(ob, gb, ln_w, ln_b, ogb);

    // 8. output projection (fp32 out)
    tgemm_kernel<<<dim3(8, 32, 1), blk256, TG_SMEM>>>(
        mk1(ogb, cWo, out, nullptr),
        VD, VD, HH, MT, HH, VD, 0, 0, 0, nullptr);
}